// round 6
// baseline (speedup 1.0000x reference)
#include <cuda_runtime.h>
#include <math.h>

#define NN    4096
#define NF    512
#define NH    64
#define NC    40
#define HEADS 4
#define NE    131072
#define ADJW  128          // 4096 bits / 32 per row
#define CAP   416          // neighbor list capacity per row (mean deg ~32)
#define ALPHA 0.2f

typedef unsigned long long ull;

// ---------------- scratch (device globals; no allocation allowed) ----------
__device__ __align__(16) unsigned g_adj[NN * ADJW];     // 2 MB bitmask adjacency
__device__ __align__(16) float    g_Wh1[HEADS * NN * NH];
__device__ __align__(16) float    g_srcT1[NN * HEADS];  // [i][h] transposed
__device__ __align__(16) float    g_dstT1[NN * HEADS];  // [i][h] transposed
__device__ __align__(16) float    g_h[NN * HEADS * NH]; // [i][h*64+c] post-elu concat
__device__ __align__(16) float    g_Wh2[NN * NC];
__device__ __align__(16) float    g_src2[NN];
__device__ __align__(16) float    g_dst2[NN];

// ---------------- packed f32x2 helpers ----------------
__device__ __forceinline__ void fma2(ull& acc, ull a, ull b) {
    asm("fma.rn.f32x2 %0, %1, %2, %0;" : "+l"(acc) : "l"(a), "l"(b));
}
__device__ __forceinline__ ull add2(ull a, ull b) {
    ull r; asm("add.rn.f32x2 %0, %1, %2;" : "=l"(r) : "l"(a), "l"(b)); return r;
}
__device__ __forceinline__ ull splat2(float v) {
    ull r; asm("mov.b64 %0, {%1, %1};" : "=l"(r) : "f"(v)); return r;
}
__device__ __forceinline__ ull pack2(float lo, float hi) {
    ull r; asm("mov.b64 %0, {%1, %2};" : "=l"(r) : "f"(lo), "f"(hi)); return r;
}
__device__ __forceinline__ float2 unpack2(ull v) {
    float2 r; asm("mov.b64 {%0, %1}, %2;" : "=f"(r.x), "=f"(r.y) : "l"(v)); return r;
}

// ---------------- warp reductions ----------------
__device__ __forceinline__ float warpMax(float v) {
#pragma unroll
    for (int o = 16; o; o >>= 1) v = fmaxf(v, __shfl_xor_sync(0xffffffffu, v, o));
    return v;
}
__device__ __forceinline__ float warpSum(float v) {
#pragma unroll
    for (int o = 16; o; o >>= 1) v += __shfl_xor_sync(0xffffffffu, v, o);
    return v;
}
__device__ __forceinline__ ull halfSum2(ull v) {
#pragma unroll
    for (int o = 1; o <= 8; o <<= 1)
        v = add2(v, __shfl_xor_sync(0xffffffffu, v, o));
    return v;
}

// ---------------- adjacency ----------------
__global__ void k_zero() {
    int i = blockIdx.x * blockDim.x + threadIdx.x;
    ((uint4*)g_adj)[i] = make_uint4(0u, 0u, 0u, 0u);
}

__global__ void k_scatter(const void* e) {
    const long long* p64 = (const long long*)e;
    bool is32 = false;
#pragma unroll
    for (int q = 0; q < 16; q++) {
        long long v = p64[q];
        if (v < 0 || v >= NN) is32 = true;
    }
    int k = blockIdx.x * blockDim.x + threadIdx.x;
    if (k >= NE) return;
    int s, d;
    if (is32) {
        const int* p = (const int*)e;
        s = p[k]; d = p[k + NE];
    } else {
        s = (int)p64[k]; d = (int)p64[k + NE];
    }
    atomicOr(&g_adj[s * ADJW + (d >> 5)], 1u << (d & 31));
}

// ---------------- layer-1 GEMM + fused src/dst epilogue --------------------
// grid (64, 2), 128 threads; 64x128 tile (2 heads); thread = 8m x 8n f32x2.
__global__ __launch_bounds__(128) void k_gemm1(const float* __restrict__ x,
                                               const float* __restrict__ W,
                                               const float* __restrict__ b,
                                               const float* __restrict__ a1) {
    __shared__ float As[2][16][68];
    __shared__ float Bs[2][16][128];
    int t  = threadIdx.x;
    int tx = t & 15, ty = t >> 4;
    int m0 = blockIdx.x * 64;
    int by = blockIdx.y;                      // heads 2*by, 2*by+1
    const float* W0  = W + (size_t)(2 * by) * NF * NH;
    const float* W1p = W0 + (size_t)NF * NH;

    const float* xp  = x + (size_t)(m0 + (t >> 1)) * NF + (t & 1) * 8;
    const float* bp0 = W0  + (size_t)ty * NH + tx * 4;
    const float* bp1 = W1p + (size_t)ty * NH + tx * 4;

    float4 ra0 = *(const float4*)(xp);
    float4 ra1 = *(const float4*)(xp + 4);
    float4 rb0 = *(const float4*)(bp0);
    float4 rb1 = *(const float4*)(bp0 + 8 * NH);
    float4 rb2 = *(const float4*)(bp1);
    float4 rb3 = *(const float4*)(bp1 + 8 * NH);

    ull acc[4][8];
#pragma unroll
    for (int p = 0; p < 4; p++)
#pragma unroll
        for (int j = 0; j < 8; j++) acc[p][j] = 0ull;

    int kh = (t & 1) * 8, mA = t >> 1;

    for (int ch = 0; ch < 32; ch++) {
        int bi = ch & 1;
        As[bi][kh + 0][mA] = ra0.x; As[bi][kh + 1][mA] = ra0.y;
        As[bi][kh + 2][mA] = ra0.z; As[bi][kh + 3][mA] = ra0.w;
        As[bi][kh + 4][mA] = ra1.x; As[bi][kh + 5][mA] = ra1.y;
        As[bi][kh + 6][mA] = ra1.z; As[bi][kh + 7][mA] = ra1.w;
        *(float4*)&Bs[bi][ty    ][tx * 4]      = rb0;
        *(float4*)&Bs[bi][ty + 8][tx * 4]      = rb1;
        *(float4*)&Bs[bi][ty    ][64 + tx * 4] = rb2;
        *(float4*)&Bs[bi][ty + 8][64 + tx * 4] = rb3;
        __syncthreads();
        if (ch < 31) {
            int ko = (ch + 1) * 16;
            ra0 = *(const float4*)(xp + ko);
            ra1 = *(const float4*)(xp + ko + 4);
            rb0 = *(const float4*)(bp0 + (size_t)ko * NH);
            rb1 = *(const float4*)(bp0 + (size_t)(ko + 8) * NH);
            rb2 = *(const float4*)(bp1 + (size_t)ko * NH);
            rb3 = *(const float4*)(bp1 + (size_t)(ko + 8) * NH);
        }
#pragma unroll
        for (int kk = 0; kk < 16; kk++) {
            ull a0 = *(const ull*)&As[bi][kk][ty * 8 + 0];
            ull a1r = *(const ull*)&As[bi][kk][ty * 8 + 2];
            ull a2 = *(const ull*)&As[bi][kk][ty * 8 + 4];
            ull a3 = *(const ull*)&As[bi][kk][ty * 8 + 6];
            float4 v0 = *(const float4*)&Bs[bi][kk][tx * 4];
            float4 v1 = *(const float4*)&Bs[bi][kk][64 + tx * 4];
            ull s0 = splat2(v0.x), s1 = splat2(v0.y), s2 = splat2(v0.z), s3 = splat2(v0.w);
            ull s4 = splat2(v1.x), s5 = splat2(v1.y), s6 = splat2(v1.z), s7 = splat2(v1.w);
            fma2(acc[0][0], a0, s0); fma2(acc[0][1], a0, s1); fma2(acc[0][2], a0, s2); fma2(acc[0][3], a0, s3);
            fma2(acc[0][4], a0, s4); fma2(acc[0][5], a0, s5); fma2(acc[0][6], a0, s6); fma2(acc[0][7], a0, s7);
            fma2(acc[1][0], a1r, s0); fma2(acc[1][1], a1r, s1); fma2(acc[1][2], a1r, s2); fma2(acc[1][3], a1r, s3);
            fma2(acc[1][4], a1r, s4); fma2(acc[1][5], a1r, s5); fma2(acc[1][6], a1r, s6); fma2(acc[1][7], a1r, s7);
            fma2(acc[2][0], a2, s0); fma2(acc[2][1], a2, s1); fma2(acc[2][2], a2, s2); fma2(acc[2][3], a2, s3);
            fma2(acc[2][4], a2, s4); fma2(acc[2][5], a2, s5); fma2(acc[2][6], a2, s6); fma2(acc[2][7], a2, s7);
            fma2(acc[3][0], a3, s0); fma2(acc[3][1], a3, s1); fma2(acc[3][2], a3, s2); fma2(acc[3][3], a3, s3);
            fma2(acc[3][4], a3, s4); fma2(acc[3][5], a3, s5); fma2(acc[3][6], a3, s6); fma2(acc[3][7], a3, s7);
        }
        __syncthreads();
    }

    int hA = 2 * by, hB = 2 * by + 1;
    float4 biasA = *(const float4*)&b[hA * NH + tx * 4];
    float4 biasB = *(const float4*)&b[hB * NH + tx * 4];

    const float* aA = a1 + hA * 2 * NH;
    const float* aB = a1 + hB * 2 * NH;
    ull apA[4], apB[4];
#pragma unroll
    for (int q = 0; q < 4; q++) {
        apA[q] = pack2(aA[tx * 4 + q], aA[NH + tx * 4 + q]);
        apB[q] = pack2(aB[tx * 4 + q], aB[NH + tx * 4 + q]);
    }

#pragma unroll
    for (int p = 0; p < 4; p++) {
        int mlo = m0 + ty * 8 + 2 * p;
        float2 c0 = unpack2(acc[p][0]), c1 = unpack2(acc[p][1]);
        float2 c2 = unpack2(acc[p][2]), c3 = unpack2(acc[p][3]);
        float2 c4 = unpack2(acc[p][4]), c5 = unpack2(acc[p][5]);
        float2 c6 = unpack2(acc[p][6]), c7 = unpack2(acc[p][7]);
        float4 vA0 = make_float4(c0.x + biasA.x, c1.x + biasA.y, c2.x + biasA.z, c3.x + biasA.w);
        float4 vA1 = make_float4(c0.y + biasA.x, c1.y + biasA.y, c2.y + biasA.z, c3.y + biasA.w);
        float4 vB0 = make_float4(c4.x + biasB.x, c5.x + biasB.y, c6.x + biasB.z, c7.x + biasB.w);
        float4 vB1 = make_float4(c4.y + biasB.x, c5.y + biasB.y, c6.y + biasB.z, c7.y + biasB.w);
        *(float4*)&g_Wh1[((size_t)hA * NN + mlo)     * NH + tx * 4] = vA0;
        *(float4*)&g_Wh1[((size_t)hA * NN + mlo + 1) * NH + tx * 4] = vA1;
        *(float4*)&g_Wh1[((size_t)hB * NN + mlo)     * NH + tx * 4] = vB0;
        *(float4*)&g_Wh1[((size_t)hB * NN + mlo + 1) * NH + tx * 4] = vB1;

        // fused src/dst partial dots + 16-lane butterfly
        ull sdA0 = 0ull, sdA1 = 0ull, sdB0 = 0ull, sdB1 = 0ull;
        fma2(sdA0, splat2(vA0.x), apA[0]); fma2(sdA0, splat2(vA0.y), apA[1]);
        fma2(sdA0, splat2(vA0.z), apA[2]); fma2(sdA0, splat2(vA0.w), apA[3]);
        fma2(sdA1, splat2(vA1.x), apA[0]); fma2(sdA1, splat2(vA1.y), apA[1]);
        fma2(sdA1, splat2(vA1.z), apA[2]); fma2(sdA1, splat2(vA1.w), apA[3]);
        fma2(sdB0, splat2(vB0.x), apB[0]); fma2(sdB0, splat2(vB0.y), apB[1]);
        fma2(sdB0, splat2(vB0.z), apB[2]); fma2(sdB0, splat2(vB0.w), apB[3]);
        fma2(sdB1, splat2(vB1.x), apB[0]); fma2(sdB1, splat2(vB1.y), apB[1]);
        fma2(sdB1, splat2(vB1.z), apB[2]); fma2(sdB1, splat2(vB1.w), apB[3]);
        sdA0 = halfSum2(sdA0); sdA1 = halfSum2(sdA1);
        sdB0 = halfSum2(sdB0); sdB1 = halfSum2(sdB1);
        if (tx == 0) {
            float2 r;
            r = unpack2(sdA0); g_srcT1[mlo * 4 + hA]       = r.x; g_dstT1[mlo * 4 + hA]       = r.y;
            r = unpack2(sdA1); g_srcT1[(mlo + 1) * 4 + hA] = r.x; g_dstT1[(mlo + 1) * 4 + hA] = r.y;
            r = unpack2(sdB0); g_srcT1[mlo * 4 + hB]       = r.x; g_dstT1[mlo * 4 + hB]       = r.y;
            r = unpack2(sdB1); g_srcT1[(mlo + 1) * 4 + hB] = r.x; g_dstT1[(mlo + 1) * 4 + hB] = r.y;
        }
    }
}

// ---------------- layer-1 sparse attention + elu + concat ----------------
// block 128 threads = one row. Block-wide gather ONCE; per-head warps do
// softmax + aggregation. Smem words pack {p | byte-offset} for a 1-LDS.64 loop.
__global__ __launch_bounds__(128) void k_att1(const float* __restrict__ ab1) {
    __shared__ unsigned short s_nbr[CAP];
    __shared__ ull            s_pj[4][CAP];
    __shared__ int            s_wtot[4];
    int i = blockIdx.x;
    int t = threadIdx.x;
    int h = t >> 5, lane = t & 31;
    int half = lane >> 4, sl = lane & 15;

    const unsigned* row = g_adj + (size_t)i * ADJW;

    // --- block-wide gather: thread t owns adjacency word t ---
    unsigned w = row[t];
    int c = __popc(w);
    int ofs = c;
#pragma unroll
    for (int o = 1; o < 32; o <<= 1) {
        int v = __shfl_up_sync(0xffffffffu, ofs, o);
        if (lane >= o) ofs += v;
    }
    if (lane == 31) s_wtot[h] = ofs;        // inclusive warp total
    __syncthreads();
    int wbase = 0;
#pragma unroll
    for (int q = 0; q < 4; q++) wbase += (q < h) ? s_wtot[q] : 0;
    int cnt = s_wtot[0] + s_wtot[1] + s_wtot[2] + s_wtot[3];
    int base = wbase + ofs - c;
    while (w) {
        int b = __ffs(w) - 1; w &= w - 1;
        if (base < CAP) s_nbr[base] = (unsigned short)(t * 32 + b);
        base++;
    }
    __syncthreads();

    // --- per-head softmax + aggregation (warp h) ---
    float srci = g_srcT1[i * 4 + h] + ab1[h];
    const char* WhB = (const char*)(g_Wh1 + (size_t)h * NN * NH) + sl * 16;
    ull accA = 0ull, accB = 0ull; float sden;

    if (cnt > 0 && cnt <= CAP) {
        float m = -1e30f;
        for (int k = lane; k < cnt; k += 32) {
            int j = s_nbr[k];
            float e = srci + g_dstT1[j * 4 + h];
            e = e > 0.f ? e : ALPHA * e;
            s_pj[h][k] = ((ull)__float_as_uint(e) << 32) | (unsigned)(j * (NH * 4));
            m = fmaxf(m, e);
        }
        m = warpMax(m);
        float s = 0.f;
        for (int k = lane; k < cnt; k += 32) {
            float* pe = (float*)&s_pj[h][k];
            float p = __expf(pe[1] - m);
            pe[1] = p; s += p;
        }
        sden = warpSum(s);
        __syncwarp();
#pragma unroll 8
        for (int k = half; k < cnt; k += 2) {
            ull wj = s_pj[h][k];
            float p = __uint_as_float((unsigned)(wj >> 32));
            float4 wv = *(const float4*)(WhB + (unsigned)wj);
            ull ps = splat2(p);
            fma2(accA, ps, pack2(wv.x, wv.y));
            fma2(accB, ps, pack2(wv.z, wv.w));
        }
    } else if (cnt == 0) {
        ull one = splat2(1.f);
        const float* Wh = g_Wh1 + (size_t)h * NN * NH;
#pragma unroll 4
        for (int j = half; j < NN; j += 2) {
            float4 wv = *(const float4*)(Wh + (size_t)j * NH + sl * 4);
            fma2(accA, one, pack2(wv.x, wv.y));
            fma2(accB, one, pack2(wv.z, wv.w));
        }
        sden = (float)NN;
    } else {
        // overflow fallback: exact serial path (never expected)
        const float* Wh = g_Wh1 + (size_t)h * NN * NH;
        float m = -1e30f;
        for (int j = 0; j < NN; j++)
            if ((row[j >> 5] >> (j & 31)) & 1u) {
                float e = srci + g_dstT1[j * 4 + h]; e = e > 0.f ? e : ALPHA * e;
                m = fmaxf(m, e);
            }
        sden = 0.f;
        for (int j = 0; j < NN; j++)
            if ((row[j >> 5] >> (j & 31)) & 1u) {
                float e = srci + g_dstT1[j * 4 + h]; e = e > 0.f ? e : ALPHA * e;
                float p = __expf(e - m); sden += p;
                float4 wv = *(const float4*)(Wh + (size_t)j * NH + sl * 4);
                if (half == 0) {
                    ull ps = splat2(p);
                    fma2(accA, ps, pack2(wv.x, wv.y));
                    fma2(accB, ps, pack2(wv.z, wv.w));
                }
            }
    }
    accA = add2(accA, __shfl_xor_sync(0xffffffffu, accA, 16));
    accB = add2(accB, __shfl_xor_sync(0xffffffffu, accB, 16));
    if (half == 0) {
        float inv = 1.f / sden;
        float2 a = unpack2(accA), bb = unpack2(accB);
        float4 v = make_float4(a.x * inv, a.y * inv, bb.x * inv, bb.y * inv);
        v.x = v.x > 0.f ? v.x : expm1f(v.x);
        v.y = v.y > 0.f ? v.y : expm1f(v.y);
        v.z = v.z > 0.f ? v.z : expm1f(v.z);
        v.w = v.w > 0.f ? v.w : expm1f(v.w);
        *(float4*)&g_h[(size_t)i * (HEADS * NH) + h * NH + sl * 4] = v;
    }
}

// ---------------- layer-2 GEMM + src/dst fold -----------------------------
__global__ __launch_bounds__(256) void k_gemm2(const float* __restrict__ Wo,
                                               const float* __restrict__ bo,
                                               const float* __restrict__ ao) {
    __shared__ float sW[256 * NC];
    int tid = threadIdx.x;
#pragma unroll
    for (int q = 0; q < 10; q++) {
        int f = tid + q * 256;
        *(float4*)&sW[f * 4] = *(const float4*)&Wo[f * 4];
    }
    __syncthreads();

    int m  = blockIdx.x * 64 + (tid >> 2);
    int g  = tid & 3;
    int cp0 = g * 5;
    const float* hr = g_h + (size_t)m * (HEADS * NH);

    ull acc[5];
#pragma unroll
    for (int u = 0; u < 5; u++)
        acc[u] = pack2(bo[2 * (cp0 + u)], bo[2 * (cp0 + u) + 1]);

    for (int k0 = 0; k0 < HEADS * NH; k0 += 4) {
        float4 hv = *(const float4*)(hr + k0);
#pragma unroll
        for (int q = 0; q < 4; q++) {
            float hvq = q == 0 ? hv.x : q == 1 ? hv.y : q == 2 ? hv.z : hv.w;
            ull hs = splat2(hvq);
            const float* wrow = sW + (k0 + q) * NC + 2 * cp0;
#pragma unroll
            for (int u = 0; u < 5; u++)
                fma2(acc[u], hs, *(const ull*)(wrow + 2 * u));
        }
    }

    float sp = 0.f, tp = 0.f;
#pragma unroll
    for (int u = 0; u < 5; u++) {
        float2 p = unpack2(acc[u]);
        int c = 2 * (cp0 + u);
        sp += p.x * ao[c]      + p.y * ao[c + 1];
        tp += p.x * ao[NC + c] + p.y * ao[NC + c + 1];
        *(float2*)&g_Wh2[(size_t)m * NC + c] = p;
    }
    sp += __shfl_xor_sync(0xffffffffu, sp, 1);
    sp += __shfl_xor_sync(0xffffffffu, sp, 2);
    tp += __shfl_xor_sync(0xffffffffu, tp, 1);
    tp += __shfl_xor_sync(0xffffffffu, tp, 2);
    if (g == 0) { g_src2[m] = sp; g_dst2[m] = tp; }
}

// ---------------- output attention + elu + log_softmax ----------------
// block 128 = 4 warps, one row per warp; packed {p|off} smem + dual acc chains.
__global__ __launch_bounds__(128) void k_att2(const float* __restrict__ abo,
                                              float* __restrict__ out) {
    __shared__ ull s_pj[4][CAP];
    int wi = threadIdx.x >> 5;
    int i  = blockIdx.x * 4 + wi;
    int lane = threadIdx.x & 31;

    const unsigned* row = g_adj + (size_t)i * ADJW;
    float srci = g_src2[i] + abo[0];

    unsigned w[4]; int myc = 0;
#pragma unroll
    for (int q = 0; q < 4; q++) { w[q] = row[lane + 32 * q]; myc += __popc(w[q]); }
    int ofs = myc;
#pragma unroll
    for (int o = 1; o < 32; o <<= 1) {
        int v = __shfl_up_sync(0xffffffffu, ofs, o);
        if (lane >= o) ofs += v;
    }
    int cnt  = __shfl_sync(0xffffffffu, ofs, 31);
    int base = ofs - myc;
#pragma unroll
    for (int q = 0; q < 4; q++) {
        unsigned ww = w[q];
        while (ww) {
            int bpos = __ffs(ww) - 1; ww &= ww - 1;
            int j = (lane + 32 * q) * 32 + bpos;
            if (base < CAP) {
                float e = srci + g_dst2[j];
                e = e > 0.f ? e : ALPHA * e;
                s_pj[wi][base] = ((ull)__float_as_uint(e) << 32) | (unsigned)(j * (NC * 4));
            }
            base++;
        }
    }
    __syncwarp();

    bool act = lane < NC / 2;      // 20 active pair-lanes
    ull acc0 = 0ull, acc1 = 0ull; float sden;

    if (cnt > 0 && cnt <= CAP) {
        float m = -1e30f;
        for (int k = lane; k < cnt; k += 32)
            m = fmaxf(m, ((const float*)&s_pj[wi][k])[1]);
        m = warpMax(m);
        float s = 0.f;
        for (int k = lane; k < cnt; k += 32) {
            float* pe = (float*)&s_pj[wi][k];
            float p = __expf(pe[1] - m);
            pe[1] = p; s += p;
        }
        sden = warpSum(s);
        __syncwarp();
        const char* wb = (const char*)g_Wh2 + lane * 8;
        int k = 0;
#pragma unroll 4
        for (; k + 1 < cnt; k += 2) {
            ull w0 = s_pj[wi][k], w1 = s_pj[wi][k + 1];
            if (act) {
                fma2(acc0, splat2(__uint_as_float((unsigned)(w0 >> 32))),
                     *(const ull*)(wb + (unsigned)w0));
                fma2(acc1, splat2(__uint_as_float((unsigned)(w1 >> 32))),
                     *(const ull*)(wb + (unsigned)w1));
            }
        }
        if (k < cnt) {
            ull w0 = s_pj[wi][k];
            if (act)
                fma2(acc0, splat2(__uint_as_float((unsigned)(w0 >> 32))),
                     *(const ull*)(wb + (unsigned)w0));
        }
    } else if (cnt == 0) {
        ull one = splat2(1.f);
        for (int j = 0; j < NN; j++)
            if (act) {
                ull wv = *(const ull*)(g_Wh2 + (size_t)j * NC + 2 * lane);
                fma2(acc0, one, wv);
            }
        sden = (float)NN;
    } else {
        float m = -1e30f;
        for (int j = 0; j < NN; j++)
            if ((row[j >> 5] >> (j & 31)) & 1u) {
                float e = srci + g_dst2[j]; e = e > 0.f ? e : ALPHA * e;
                m = fmaxf(m, e);
            }
        sden = 0.f;
        for (int j = 0; j < NN; j++)
            if ((row[j >> 5] >> (j & 31)) & 1u) {
                float e = srci + g_dst2[j]; e = e > 0.f ? e : ALPHA * e;
                float p = __expf(e - m); sden += p;
                if (act) {
                    ull wv = *(const ull*)(g_Wh2 + (size_t)j * NC + 2 * lane);
                    fma2(acc0, splat2(p), wv);
                }
            }
    }
    ull acc = add2(acc0, acc1);
    float inv = 1.f / sden;
    float2 v = unpack2(acc);
    v.x *= inv; v.y *= inv;
    if (act) {
        v.x = v.x > 0.f ? v.x : expm1f(v.x);
        v.y = v.y > 0.f ? v.y : expm1f(v.y);
    }
    float mx = act ? fmaxf(v.x, v.y) : -1e30f;
    mx = warpMax(mx);
    float se = act ? (__expf(v.x - mx) + __expf(v.y - mx)) : 0.f;
    se = warpSum(se);
    float ls = mx + __logf(se);

    if (act)
        *(float2*)&out[(size_t)i * NC + 2 * lane] = make_float2(v.x - ls, v.y - ls);
}

// ---------------- launcher ----------------
extern "C" void kernel_launch(void* const* d_in, const int* in_sizes, int n_in,
                              void* d_out, int out_size) {
    const float* x   = (const float*)d_in[0];
    const void*  ei  = d_in[1];
    const float* W1  = (const float*)d_in[2];
    const float* b1  = (const float*)d_in[3];
    const float* a1  = (const float*)d_in[4];
    const float* ab1 = (const float*)d_in[5];
    const float* Wo  = (const float*)d_in[6];
    const float* bo  = (const float*)d_in[7];
    const float* ao  = (const float*)d_in[8];
    const float* abo = (const float*)d_in[9];
    float* out = (float*)d_out;

    k_zero<<<NN * ADJW / 4 / 256, 256>>>();
    k_scatter<<<NE / 256, 256>>>(ei);
    k_gemm1<<<dim3(64, 2), 128>>>(x, W1, b1, a1);
    k_att1<<<NN, 128>>>(ab1);
    k_gemm2<<<64, 256>>>(Wo, bo, ao);
    k_att2<<<NN / 4, 128>>>(abo, out);
}

// round 8
// speedup vs baseline: 1.0737x; 1.0737x over previous
#include <cuda_runtime.h>
#include <math.h>

#define NN    4096
#define NF    512
#define NH    64
#define NC    40
#define HEADS 4
#define NE    131072
#define ADJW  128          // 4096 bits / 32 per row
#define CAP   192          // neighbor capacity (mean deg 32, Poisson tail << CAP)
#define ALPHA 0.2f

typedef unsigned long long ull;

// ---------------- scratch (device globals; no allocation allowed) ----------
__device__ __align__(16) unsigned       g_adj[NN * ADJW];
__device__ __align__(16) float          g_Wh1[HEADS * NN * NH];
__device__ __align__(16) float          g_srcT1[NN * HEADS];  // [i][h]
__device__ __align__(16) float          g_dstT1[NN * HEADS];  // [i][h]
__device__ __align__(16) float          g_h[NN * HEADS * NH];
__device__ __align__(16) float          g_Wh2[NN * NC];
__device__ __align__(16) float          g_src2[NN];
__device__ __align__(16) float          g_dst2[NN];
__device__ __align__(16) unsigned short g_nbr[NN * CAP];      // CSR handoff
__device__                int           g_cnt[NN];

// ---------------- packed f32x2 helpers ----------------
__device__ __forceinline__ void fma2(ull& acc, ull a, ull b) {
    asm("fma.rn.f32x2 %0, %1, %2, %0;" : "+l"(acc) : "l"(a), "l"(b));
}
__device__ __forceinline__ ull add2(ull a, ull b) {
    ull r; asm("add.rn.f32x2 %0, %1, %2;" : "=l"(r) : "l"(a), "l"(b)); return r;
}
__device__ __forceinline__ ull splat2(float v) {
    ull r; asm("mov.b64 %0, {%1, %1};" : "=l"(r) : "f"(v)); return r;
}
__device__ __forceinline__ ull pack2(float lo, float hi) {
    ull r; asm("mov.b64 %0, {%1, %2};" : "=l"(r) : "f"(lo), "f"(hi)); return r;
}
__device__ __forceinline__ float2 unpack2(ull v) {
    float2 r; asm("mov.b64 {%0, %1}, %2;" : "=f"(r.x), "=f"(r.y) : "l"(v)); return r;
}

// ---------------- warp reductions ----------------
__device__ __forceinline__ float warpMax(float v) {
#pragma unroll
    for (int o = 16; o; o >>= 1) v = fmaxf(v, __shfl_xor_sync(0xffffffffu, v, o));
    return v;
}
__device__ __forceinline__ float warpSum(float v) {
#pragma unroll
    for (int o = 16; o; o >>= 1) v += __shfl_xor_sync(0xffffffffu, v, o);
    return v;
}
__device__ __forceinline__ ull halfSum2(ull v) {
#pragma unroll
    for (int o = 1; o <= 8; o <<= 1)
        v = add2(v, __shfl_xor_sync(0xffffffffu, v, o));
    return v;
}

// ---------------- adjacency ----------------
__global__ void k_zero() {
    int i = blockIdx.x * blockDim.x + threadIdx.x;
    ((uint4*)g_adj)[i] = make_uint4(0u, 0u, 0u, 0u);
}

__global__ void k_scatter(const void* e) {
    const long long* p64 = (const long long*)e;
    bool is32 = false;
#pragma unroll
    for (int q = 0; q < 16; q++) {
        long long v = p64[q];
        if (v < 0 || v >= NN) is32 = true;
    }
    int k = blockIdx.x * blockDim.x + threadIdx.x;
    if (k >= NE) return;
    int s, d;
    if (is32) {
        const int* p = (const int*)e;
        s = p[k]; d = p[k + NE];
    } else {
        s = (int)p64[k]; d = (int)p64[k + NE];
    }
    atomicOr(&g_adj[s * ADJW + (d >> 5)], 1u << (d & 31));
}

// ---------------- layer-1 GEMM + fused src/dst epilogue --------------------
__global__ __launch_bounds__(128) void k_gemm1(const float* __restrict__ x,
                                               const float* __restrict__ W,
                                               const float* __restrict__ b,
                                               const float* __restrict__ a1) {
    __shared__ float As[2][16][68];
    __shared__ float Bs[2][16][128];
    int t  = threadIdx.x;
    int tx = t & 15, ty = t >> 4;
    int m0 = blockIdx.x * 64;
    int by = blockIdx.y;
    const float* W0  = W + (size_t)(2 * by) * NF * NH;
    const float* W1p = W0 + (size_t)NF * NH;

    const float* xp  = x + (size_t)(m0 + (t >> 1)) * NF + (t & 1) * 8;
    const float* bp0 = W0  + (size_t)ty * NH + tx * 4;
    const float* bp1 = W1p + (size_t)ty * NH + tx * 4;

    float4 ra0 = *(const float4*)(xp);
    float4 ra1 = *(const float4*)(xp + 4);
    float4 rb0 = *(const float4*)(bp0);
    float4 rb1 = *(const float4*)(bp0 + 8 * NH);
    float4 rb2 = *(const float4*)(bp1);
    float4 rb3 = *(const float4*)(bp1 + 8 * NH);

    ull acc[4][8];
#pragma unroll
    for (int p = 0; p < 4; p++)
#pragma unroll
        for (int j = 0; j < 8; j++) acc[p][j] = 0ull;

    int kh = (t & 1) * 8, mA = t >> 1;

    for (int ch = 0; ch < 32; ch++) {
        int bi = ch & 1;
        As[bi][kh + 0][mA] = ra0.x; As[bi][kh + 1][mA] = ra0.y;
        As[bi][kh + 2][mA] = ra0.z; As[bi][kh + 3][mA] = ra0.w;
        As[bi][kh + 4][mA] = ra1.x; As[bi][kh + 5][mA] = ra1.y;
        As[bi][kh + 6][mA] = ra1.z; As[bi][kh + 7][mA] = ra1.w;
        *(float4*)&Bs[bi][ty    ][tx * 4]      = rb0;
        *(float4*)&Bs[bi][ty + 8][tx * 4]      = rb1;
        *(float4*)&Bs[bi][ty    ][64 + tx * 4] = rb2;
        *(float4*)&Bs[bi][ty + 8][64 + tx * 4] = rb3;
        __syncthreads();
        if (ch < 31) {
            int ko = (ch + 1) * 16;
            ra0 = *(const float4*)(xp + ko);
            ra1 = *(const float4*)(xp + ko + 4);
            rb0 = *(const float4*)(bp0 + (size_t)ko * NH);
            rb1 = *(const float4*)(bp0 + (size_t)(ko + 8) * NH);
            rb2 = *(const float4*)(bp1 + (size_t)ko * NH);
            rb3 = *(const float4*)(bp1 + (size_t)(ko + 8) * NH);
        }
#pragma unroll
        for (int kk = 0; kk < 16; kk++) {
            ull a0 = *(const ull*)&As[bi][kk][ty * 8 + 0];
            ull a1r = *(const ull*)&As[bi][kk][ty * 8 + 2];
            ull a2 = *(const ull*)&As[bi][kk][ty * 8 + 4];
            ull a3 = *(const ull*)&As[bi][kk][ty * 8 + 6];
            float4 v0 = *(const float4*)&Bs[bi][kk][tx * 4];
            float4 v1 = *(const float4*)&Bs[bi][kk][64 + tx * 4];
            ull s0 = splat2(v0.x), s1 = splat2(v0.y), s2 = splat2(v0.z), s3 = splat2(v0.w);
            ull s4 = splat2(v1.x), s5 = splat2(v1.y), s6 = splat2(v1.z), s7 = splat2(v1.w);
            fma2(acc[0][0], a0, s0); fma2(acc[0][1], a0, s1); fma2(acc[0][2], a0, s2); fma2(acc[0][3], a0, s3);
            fma2(acc[0][4], a0, s4); fma2(acc[0][5], a0, s5); fma2(acc[0][6], a0, s6); fma2(acc[0][7], a0, s7);
            fma2(acc[1][0], a1r, s0); fma2(acc[1][1], a1r, s1); fma2(acc[1][2], a1r, s2); fma2(acc[1][3], a1r, s3);
            fma2(acc[1][4], a1r, s4); fma2(acc[1][5], a1r, s5); fma2(acc[1][6], a1r, s6); fma2(acc[1][7], a1r, s7);
            fma2(acc[2][0], a2, s0); fma2(acc[2][1], a2, s1); fma2(acc[2][2], a2, s2); fma2(acc[2][3], a2, s3);
            fma2(acc[2][4], a2, s4); fma2(acc[2][5], a2, s5); fma2(acc[2][6], a2, s6); fma2(acc[2][7], a2, s7);
            fma2(acc[3][0], a3, s0); fma2(acc[3][1], a3, s1); fma2(acc[3][2], a3, s2); fma2(acc[3][3], a3, s3);
            fma2(acc[3][4], a3, s4); fma2(acc[3][5], a3, s5); fma2(acc[3][6], a3, s6); fma2(acc[3][7], a3, s7);
        }
        __syncthreads();
    }

    int hA = 2 * by, hB = 2 * by + 1;
    float4 biasA = *(const float4*)&b[hA * NH + tx * 4];
    float4 biasB = *(const float4*)&b[hB * NH + tx * 4];

    const float* aA = a1 + hA * 2 * NH;
    const float* aB = a1 + hB * 2 * NH;
    ull apA[4], apB[4];
#pragma unroll
    for (int q = 0; q < 4; q++) {
        apA[q] = pack2(aA[tx * 4 + q], aA[NH + tx * 4 + q]);
        apB[q] = pack2(aB[tx * 4 + q], aB[NH + tx * 4 + q]);
    }

#pragma unroll
    for (int p = 0; p < 4; p++) {
        int mlo = m0 + ty * 8 + 2 * p;
        float2 c0 = unpack2(acc[p][0]), c1 = unpack2(acc[p][1]);
        float2 c2 = unpack2(acc[p][2]), c3 = unpack2(acc[p][3]);
        float2 c4 = unpack2(acc[p][4]), c5 = unpack2(acc[p][5]);
        float2 c6 = unpack2(acc[p][6]), c7 = unpack2(acc[p][7]);
        float4 vA0 = make_float4(c0.x + biasA.x, c1.x + biasA.y, c2.x + biasA.z, c3.x + biasA.w);
        float4 vA1 = make_float4(c0.y + biasA.x, c1.y + biasA.y, c2.y + biasA.z, c3.y + biasA.w);
        float4 vB0 = make_float4(c4.x + biasB.x, c5.x + biasB.y, c6.x + biasB.z, c7.x + biasB.w);
        float4 vB1 = make_float4(c4.y + biasB.x, c5.y + biasB.y, c6.y + biasB.z, c7.y + biasB.w);
        *(float4*)&g_Wh1[((size_t)hA * NN + mlo)     * NH + tx * 4] = vA0;
        *(float4*)&g_Wh1[((size_t)hA * NN + mlo + 1) * NH + tx * 4] = vA1;
        *(float4*)&g_Wh1[((size_t)hB * NN + mlo)     * NH + tx * 4] = vB0;
        *(float4*)&g_Wh1[((size_t)hB * NN + mlo + 1) * NH + tx * 4] = vB1;

        ull sdA0 = 0ull, sdA1 = 0ull, sdB0 = 0ull, sdB1 = 0ull;
        fma2(sdA0, splat2(vA0.x), apA[0]); fma2(sdA0, splat2(vA0.y), apA[1]);
        fma2(sdA0, splat2(vA0.z), apA[2]); fma2(sdA0, splat2(vA0.w), apA[3]);
        fma2(sdA1, splat2(vA1.x), apA[0]); fma2(sdA1, splat2(vA1.y), apA[1]);
        fma2(sdA1, splat2(vA1.z), apA[2]); fma2(sdA1, splat2(vA1.w), apA[3]);
        fma2(sdB0, splat2(vB0.x), apB[0]); fma2(sdB0, splat2(vB0.y), apB[1]);
        fma2(sdB0, splat2(vB0.z), apB[2]); fma2(sdB0, splat2(vB0.w), apB[3]);
        fma2(sdB1, splat2(vB1.x), apB[0]); fma2(sdB1, splat2(vB1.y), apB[1]);
        fma2(sdB1, splat2(vB1.z), apB[2]); fma2(sdB1, splat2(vB1.w), apB[3]);
        sdA0 = halfSum2(sdA0); sdA1 = halfSum2(sdA1);
        sdB0 = halfSum2(sdB0); sdB1 = halfSum2(sdB1);
        if (tx == 0) {
            float2 r;
            r = unpack2(sdA0); g_srcT1[mlo * 4 + hA]       = r.x; g_dstT1[mlo * 4 + hA]       = r.y;
            r = unpack2(sdA1); g_srcT1[(mlo + 1) * 4 + hA] = r.x; g_dstT1[(mlo + 1) * 4 + hA] = r.y;
            r = unpack2(sdB0); g_srcT1[mlo * 4 + hB]       = r.x; g_dstT1[mlo * 4 + hB]       = r.y;
            r = unpack2(sdB1); g_srcT1[(mlo + 1) * 4 + hB] = r.x; g_dstT1[(mlo + 1) * 4 + hB] = r.y;
        }
    }
}

// ---------------- layer-1 sparse attention + elu + concat ----------------
// block 128 = one row. Block-wide gather (with dstT1 float4 prefetch to smem),
// CSR list written to global for att2; per-head warps do softmax + aggregation.
__global__ __launch_bounds__(128) void k_att1(const float* __restrict__ ab1) {
    __shared__ unsigned short s_nbr[CAP];
    __shared__ float4         s_dst[CAP];
    __shared__ float          s_p[4][CAP];
    __shared__ int            s_wtot[4];
    int i = blockIdx.x;
    int t = threadIdx.x;
    int h = t >> 5, lane = t & 31;
    int half = lane >> 4, sl = lane & 15;

    const unsigned* row = g_adj + (size_t)i * ADJW;

    // --- block-wide gather ---
    unsigned w = row[t];
    int c = __popc(w);
    int ofs = c;
#pragma unroll
    for (int o = 1; o < 32; o <<= 1) {
        int v = __shfl_up_sync(0xffffffffu, ofs, o);
        if (lane >= o) ofs += v;
    }
    if (lane == 31) s_wtot[h] = ofs;
    __syncthreads();
    int wbase = 0;
#pragma unroll
    for (int q = 0; q < 4; q++) wbase += (q < h) ? s_wtot[q] : 0;
    int cnt = s_wtot[0] + s_wtot[1] + s_wtot[2] + s_wtot[3];
    int base = wbase + ofs - c;
    while (w) {
        int b = __ffs(w) - 1; w &= w - 1;
        int j = t * 32 + b;
        if (base < CAP) {
            s_nbr[base] = (unsigned short)j;
            s_dst[base] = *(const float4*)&g_dstT1[j * 4];
        }
        base++;
    }
    __syncthreads();

    // CSR handoff for att2
    if (t == 0) g_cnt[i] = cnt;
    int cc = cnt < CAP ? cnt : CAP;
    for (int k = t; k < cc; k += 128) g_nbr[i * CAP + k] = s_nbr[k];

    // --- per-head softmax + aggregation (warp h) ---
    float srci = g_srcT1[i * 4 + h] + ab1[h];
    const float* Wh = g_Wh1 + (size_t)h * NN * NH;
    ull accA = 0ull, accB = 0ull; float sden;

    if (cnt > 0 && cnt <= CAP) {
        float m = -1e30f;
        for (int k = lane; k < cnt; k += 32) {
            float e = srci + ((const float*)&s_dst[k])[h];
            e = e > 0.f ? e : ALPHA * e;
            s_p[h][k] = e;
            m = fmaxf(m, e);
        }
        m = warpMax(m);
        float s = 0.f;
        for (int k = lane; k < cnt; k += 32) {
            float p = __expf(s_p[h][k] - m); s_p[h][k] = p; s += p;
        }
        sden = warpSum(s);
        __syncwarp();
#pragma unroll 4
        for (int k = half; k < cnt; k += 2) {
            float p = s_p[h][k];
            int j = s_nbr[k];
            float4 wv = *(const float4*)(Wh + (size_t)j * NH + sl * 4);
            ull ps = splat2(p);
            fma2(accA, ps, pack2(wv.x, wv.y));
            fma2(accB, ps, pack2(wv.z, wv.w));
        }
    } else if (cnt == 0) {
        ull one = splat2(1.f);
#pragma unroll 4
        for (int j = half; j < NN; j += 2) {
            float4 wv = *(const float4*)(Wh + (size_t)j * NH + sl * 4);
            fma2(accA, one, pack2(wv.x, wv.y));
            fma2(accB, one, pack2(wv.z, wv.w));
        }
        sden = (float)NN;
    } else {
        // overflow fallback: exact serial path (never expected)
        float m = -1e30f;
        for (int j = 0; j < NN; j++)
            if ((row[j >> 5] >> (j & 31)) & 1u) {
                float e = srci + g_dstT1[j * 4 + h]; e = e > 0.f ? e : ALPHA * e;
                m = fmaxf(m, e);
            }
        sden = 0.f;
        for (int j = 0; j < NN; j++)
            if ((row[j >> 5] >> (j & 31)) & 1u) {
                float e = srci + g_dstT1[j * 4 + h]; e = e > 0.f ? e : ALPHA * e;
                float p = __expf(e - m); sden += p;
                float4 wv = *(const float4*)(Wh + (size_t)j * NH + sl * 4);
                if (half == 0) {
                    ull ps = splat2(p);
                    fma2(accA, ps, pack2(wv.x, wv.y));
                    fma2(accB, ps, pack2(wv.z, wv.w));
                }
            }
    }
    accA = add2(accA, __shfl_xor_sync(0xffffffffu, accA, 16));
    accB = add2(accB, __shfl_xor_sync(0xffffffffu, accB, 16));
    if (half == 0) {
        float inv = 1.f / sden;
        float2 a = unpack2(accA), bb = unpack2(accB);
        float4 v = make_float4(a.x * inv, a.y * inv, bb.x * inv, bb.y * inv);
        v.x = v.x > 0.f ? v.x : expm1f(v.x);
        v.y = v.y > 0.f ? v.y : expm1f(v.y);
        v.z = v.z > 0.f ? v.z : expm1f(v.z);
        v.w = v.w > 0.f ? v.w : expm1f(v.w);
        *(float4*)&g_h[(size_t)i * (HEADS * NH) + h * NH + sl * 4] = v;
    }
}

// ---------------- layer-2 GEMM + src/dst fold -----------------------------
__global__ __launch_bounds__(256) void k_gemm2(const float* __restrict__ Wo,
                                               const float* __restrict__ bo,
                                               const float* __restrict__ ao) {
    __shared__ float sW[256 * NC];
    int tid = threadIdx.x;
#pragma unroll
    for (int q = 0; q < 10; q++) {
        int f = tid + q * 256;
        *(float4*)&sW[f * 4] = *(const float4*)&Wo[f * 4];
    }
    __syncthreads();

    int m  = blockIdx.x * 64 + (tid >> 2);
    int g  = tid & 3;
    int cp0 = g * 5;
    const float* hr = g_h + (size_t)m * (HEADS * NH);

    ull acc[5];
#pragma unroll
    for (int u = 0; u < 5; u++)
        acc[u] = pack2(bo[2 * (cp0 + u)], bo[2 * (cp0 + u) + 1]);

    for (int k0 = 0; k0 < HEADS * NH; k0 += 4) {
        float4 hv = *(const float4*)(hr + k0);
#pragma unroll
        for (int q = 0; q < 4; q++) {
            float hvq = q == 0 ? hv.x : q == 1 ? hv.y : q == 2 ? hv.z : hv.w;
            ull hs = splat2(hvq);
            const float* wrow = sW + (k0 + q) * NC + 2 * cp0;
#pragma unroll
            for (int u = 0; u < 5; u++)
                fma2(acc[u], hs, *(const ull*)(wrow + 2 * u));
        }
    }

    float sp = 0.f, tp = 0.f;
#pragma unroll
    for (int u = 0; u < 5; u++) {
        float2 p = unpack2(acc[u]);
        int c = 2 * (cp0 + u);
        sp += p.x * ao[c]      + p.y * ao[c + 1];
        tp += p.x * ao[NC + c] + p.y * ao[NC + c + 1];
        *(float2*)&g_Wh2[(size_t)m * NC + c] = p;
    }
    sp += __shfl_xor_sync(0xffffffffu, sp, 1);
    sp += __shfl_xor_sync(0xffffffffu, sp, 2);
    tp += __shfl_xor_sync(0xffffffffu, tp, 1);
    tp += __shfl_xor_sync(0xffffffffu, tp, 2);
    if (g == 0) { g_src2[m] = sp; g_dst2[m] = tp; }
}

// ---------------- output attention + elu + log_softmax ----------------
// block 128 = 4 warps, one row per warp; neighbor lists from att1's CSR.
__global__ __launch_bounds__(128) void k_att2(const float* __restrict__ abo,
                                              float* __restrict__ out) {
    __shared__ float          s_pe[4][CAP];
    __shared__ unsigned short s_nb[4][CAP];
    int wi = threadIdx.x >> 5;
    int i  = blockIdx.x * 4 + wi;
    int lane = threadIdx.x & 31;

    int cnt = g_cnt[i];
    float srci = g_src2[i] + abo[0];

    bool act = lane < NC / 2;      // 20 active pair-lanes
    ull acc = 0ull; float sden;

    if (cnt > 0 && cnt <= CAP) {
        const unsigned short* nb = g_nbr + i * CAP;
        float m = -1e30f;
        for (int k = lane; k < cnt; k += 32) {
            int j = nb[k];
            s_nb[wi][k] = (unsigned short)j;
            float e = srci + g_dst2[j];
            e = e > 0.f ? e : ALPHA * e;
            s_pe[wi][k] = e;
            m = fmaxf(m, e);
        }
        m = warpMax(m);
        float s = 0.f;
        for (int k = lane; k < cnt; k += 32) {
            float p = __expf(s_pe[wi][k] - m); s_pe[wi][k] = p; s += p;
        }
        sden = warpSum(s);
        __syncwarp();
#pragma unroll 4
        for (int k = 0; k < cnt; k++) {
            float p = s_pe[wi][k];
            int j = s_nb[wi][k];
            if (act) {
                ull wv = *(const ull*)(g_Wh2 + (size_t)j * NC + 2 * lane);
                fma2(acc, splat2(p), wv);
            }
        }
    } else if (cnt == 0) {
        ull one = splat2(1.f);
        for (int j = 0; j < NN; j++)
            if (act) {
                ull wv = *(const ull*)(g_Wh2 + (size_t)j * NC + 2 * lane);
                fma2(acc, one, wv);
            }
        sden = (float)NN;
    } else {
        // overflow fallback: exact serial bitmask path
        const unsigned* row = g_adj + (size_t)i * ADJW;
        float m = -1e30f;
        for (int j = 0; j < NN; j++)
            if ((row[j >> 5] >> (j & 31)) & 1u) {
                float e = srci + g_dst2[j]; e = e > 0.f ? e : ALPHA * e;
                m = fmaxf(m, e);
            }
        sden = 0.f;
        for (int j = 0; j < NN; j++)
            if ((row[j >> 5] >> (j & 31)) & 1u) {
                float e = srci + g_dst2[j]; e = e > 0.f ? e : ALPHA * e;
                float p = __expf(e - m); sden += p;
                if (act) {
                    ull wv = *(const ull*)(g_Wh2 + (size_t)j * NC + 2 * lane);
                    fma2(acc, splat2(p), wv);
                }
            }
    }
    float inv = 1.f / sden;
    float2 v = unpack2(acc);
    v.x *= inv; v.y *= inv;
    if (act) {
        v.x = v.x > 0.f ? v.x : expm1f(v.x);
        v.y = v.y > 0.f ? v.y : expm1f(v.y);
    }
    float mx = act ? fmaxf(v.x, v.y) : -1e30f;
    mx = warpMax(mx);
    float se = act ? (__expf(v.x - mx) + __expf(v.y - mx)) : 0.f;
    se = warpSum(se);
    float ls = mx + __logf(se);

    if (act)
        *(float2*)&out[(size_t)i * NC + 2 * lane] = make_float2(v.x - ls, v.y - ls);
}

// ---------------- launcher ----------------
extern "C" void kernel_launch(void* const* d_in, const int* in_sizes, int n_in,
                              void* d_out, int out_size) {
    const float* x   = (const float*)d_in[0];
    const void*  ei  = d_in[1];
    const float* W1  = (const float*)d_in[2];
    const float* b1  = (const float*)d_in[3];
    const float* a1  = (const float*)d_in[4];
    const float* ab1 = (const float*)d_in[5];
    const float* Wo  = (const float*)d_in[6];
    const float* bo  = (const float*)d_in[7];
    const float* ao  = (const float*)d_in[8];
    const float* abo = (const float*)d_in[9];
    float* out = (float*)d_out;

    k_zero<<<NN * ADJW / 4 / 256, 256>>>();
    k_scatter<<<NE / 256, 256>>>(ei);
    k_gemm1<<<dim3(64, 2), 128>>>(x, W1, b1, a1);
    k_att1<<<NN, 128>>>(ab1);
    k_gemm2<<<64, 256>>>(Wo, bo, ao);
    k_att2<<<NN / 4, 128>>>(abo, out);
}

// round 15
// speedup vs baseline: 1.0750x; 1.0012x over previous
#include <cuda_runtime.h>
#include <math.h>

#define NN    4096
#define NF    512
#define NH    64
#define NC    40
#define HEADS 4
#define NE    131072
#define ADJW  128          // 4096 bits / 32 per row
#define CAP   192          // neighbor capacity (mean deg 32)
#define ALPHA 0.2f

typedef unsigned long long ull;

// ---------------- scratch (device globals; no allocation allowed) ----------
__device__ __align__(16) unsigned       g_adj[NN * ADJW];
__device__ __align__(16) unsigned short g_Wh1h[HEADS * NN * NH];  // fp16 Wh1
__device__ __align__(16) float          g_srcT1[NN * HEADS];  // [i][h]
__device__ __align__(16) float          g_dstT1[NN * HEADS];  // [i][h]
__device__ __align__(16) float          g_h[NN * HEADS * NH];
__device__ __align__(16) float          g_Wh2[NN * NC];
__device__ __align__(16) float          g_src2[NN];
__device__ __align__(16) float          g_dst2[NN];
__device__ __align__(16) unsigned short g_nbr[NN * CAP];      // CSR handoff
__device__                int           g_cnt[NN];

// ---------------- packed f32x2 helpers ----------------
__device__ __forceinline__ void fma2(ull& acc, ull a, ull b) {
    asm("fma.rn.f32x2 %0, %1, %2, %0;" : "+l"(acc) : "l"(a), "l"(b));
}
__device__ __forceinline__ ull add2(ull a, ull b) {
    ull r; asm("add.rn.f32x2 %0, %1, %2;" : "=l"(r) : "l"(a), "l"(b)); return r;
}
__device__ __forceinline__ ull splat2(float v) {
    ull r; asm("mov.b64 %0, {%1, %1};" : "=l"(r) : "f"(v)); return r;
}
__device__ __forceinline__ ull pack2(float lo, float hi) {
    ull r; asm("mov.b64 %0, {%1, %2};" : "=l"(r) : "f"(lo), "f"(hi)); return r;
}
__device__ __forceinline__ float2 unpack2(ull v) {
    float2 r; asm("mov.b64 {%0, %1}, %2;" : "=f"(r.x), "=f"(r.y) : "l"(v)); return r;
}

// ---------------- fp16 pack/unpack (header-free) ----------------
// f2h2(lo, hi): pack two floats into one f16x2 word (lo in low half)
__device__ __forceinline__ unsigned f2h2(float lo, float hi) {
    unsigned r;
    asm("cvt.rn.f16x2.f32 %0, %1, %2;" : "=r"(r) : "f"(hi), "f"(lo));
    return r;
}
// h2f: unpack f16x2 word to float2 (x = low half)
__device__ __forceinline__ float2 h2f(unsigned h) {
    float2 r;
    asm("{.reg .f16 l, u; mov.b32 {l, u}, %2; cvt.f32.f16 %0, l; cvt.f32.f16 %1, u;}" : "=f"(r.x), "=f"(r.y) : "r"(h));
    return r;
}

// ---------------- warp reductions ----------------
__device__ __forceinline__ float warpMax(float v) {
#pragma unroll
    for (int o = 16; o; o >>= 1) v = fmaxf(v, __shfl_xor_sync(0xffffffffu, v, o));
    return v;
}
__device__ __forceinline__ float warpSum(float v) {
#pragma unroll
    for (int o = 16; o; o >>= 1) v += __shfl_xor_sync(0xffffffffu, v, o);
    return v;
}
__device__ __forceinline__ ull halfSum2(ull v) {
#pragma unroll
    for (int o = 1; o <= 8; o <<= 1)
        v = add2(v, __shfl_xor_sync(0xffffffffu, v, o));
    return v;
}

// ---------------- adjacency ----------------
__global__ void k_zero() {
    int i = blockIdx.x * blockDim.x + threadIdx.x;
    ((uint4*)g_adj)[i] = make_uint4(0u, 0u, 0u, 0u);
}

__global__ void k_scatter(const void* e) {
    const long long* p64 = (const long long*)e;
    bool is32 = false;
#pragma unroll
    for (int q = 0; q < 16; q++) {
        long long v = p64[q];
        if (v < 0 || v >= NN) is32 = true;
    }
    int k = blockIdx.x * blockDim.x + threadIdx.x;
    if (k >= NE) return;
    int s, d;
    if (is32) {
        const int* p = (const int*)e;
        s = p[k]; d = p[k + NE];
    } else {
        s = (int)p64[k]; d = (int)p64[k + NE];
    }
    atomicOr(&g_adj[s * ADJW + (d >> 5)], 1u << (d & 31));
}

// ---------------- layer-1 GEMM + fused src/dst epilogue --------------------
// grid (64, 2), 128 threads; 64x128 tile (2 heads); thread = 8m x 8n f32x2.
// Epilogue stores Wh1 as fp16 (halves att1's aggregation traffic); src/dst
// dots stay fp32.
__global__ __launch_bounds__(128) void k_gemm1(const float* __restrict__ x,
                                               const float* __restrict__ W,
                                               const float* __restrict__ b,
                                               const float* __restrict__ a1) {
    __shared__ float As[2][16][68];
    __shared__ float Bs[2][16][128];
    int t  = threadIdx.x;
    int tx = t & 15, ty = t >> 4;
    int m0 = blockIdx.x * 64;
    int by = blockIdx.y;
    const float* W0  = W + (size_t)(2 * by) * NF * NH;
    const float* W1p = W0 + (size_t)NF * NH;

    const float* xp  = x + (size_t)(m0 + (t >> 1)) * NF + (t & 1) * 8;
    const float* bp0 = W0  + (size_t)ty * NH + tx * 4;
    const float* bp1 = W1p + (size_t)ty * NH + tx * 4;

    float4 ra0 = *(const float4*)(xp);
    float4 ra1 = *(const float4*)(xp + 4);
    float4 rb0 = *(const float4*)(bp0);
    float4 rb1 = *(const float4*)(bp0 + 8 * NH);
    float4 rb2 = *(const float4*)(bp1);
    float4 rb3 = *(const float4*)(bp1 + 8 * NH);

    ull acc[4][8];
#pragma unroll
    for (int p = 0; p < 4; p++)
#pragma unroll
        for (int j = 0; j < 8; j++) acc[p][j] = 0ull;

    int kh = (t & 1) * 8, mA = t >> 1;

    for (int ch = 0; ch < 32; ch++) {
        int bi = ch & 1;
        As[bi][kh + 0][mA] = ra0.x; As[bi][kh + 1][mA] = ra0.y;
        As[bi][kh + 2][mA] = ra0.z; As[bi][kh + 3][mA] = ra0.w;
        As[bi][kh + 4][mA] = ra1.x; As[bi][kh + 5][mA] = ra1.y;
        As[bi][kh + 6][mA] = ra1.z; As[bi][kh + 7][mA] = ra1.w;
        *(float4*)&Bs[bi][ty    ][tx * 4]      = rb0;
        *(float4*)&Bs[bi][ty + 8][tx * 4]      = rb1;
        *(float4*)&Bs[bi][ty    ][64 + tx * 4] = rb2;
        *(float4*)&Bs[bi][ty + 8][64 + tx * 4] = rb3;
        __syncthreads();
        if (ch < 31) {
            int ko = (ch + 1) * 16;
            ra0 = *(const float4*)(xp + ko);
            ra1 = *(const float4*)(xp + ko + 4);
            rb0 = *(const float4*)(bp0 + (size_t)ko * NH);
            rb1 = *(const float4*)(bp0 + (size_t)(ko + 8) * NH);
            rb2 = *(const float4*)(bp1 + (size_t)ko * NH);
            rb3 = *(const float4*)(bp1 + (size_t)(ko + 8) * NH);
        }
#pragma unroll
        for (int kk = 0; kk < 16; kk++) {
            ull a0 = *(const ull*)&As[bi][kk][ty * 8 + 0];
            ull a1r = *(const ull*)&As[bi][kk][ty * 8 + 2];
            ull a2 = *(const ull*)&As[bi][kk][ty * 8 + 4];
            ull a3 = *(const ull*)&As[bi][kk][ty * 8 + 6];
            float4 v0 = *(const float4*)&Bs[bi][kk][tx * 4];
            float4 v1 = *(const float4*)&Bs[bi][kk][64 + tx * 4];
            ull s0 = splat2(v0.x), s1 = splat2(v0.y), s2 = splat2(v0.z), s3 = splat2(v0.w);
            ull s4 = splat2(v1.x), s5 = splat2(v1.y), s6 = splat2(v1.z), s7 = splat2(v1.w);
            fma2(acc[0][0], a0, s0); fma2(acc[0][1], a0, s1); fma2(acc[0][2], a0, s2); fma2(acc[0][3], a0, s3);
            fma2(acc[0][4], a0, s4); fma2(acc[0][5], a0, s5); fma2(acc[0][6], a0, s6); fma2(acc[0][7], a0, s7);
            fma2(acc[1][0], a1r, s0); fma2(acc[1][1], a1r, s1); fma2(acc[1][2], a1r, s2); fma2(acc[1][3], a1r, s3);
            fma2(acc[1][4], a1r, s4); fma2(acc[1][5], a1r, s5); fma2(acc[1][6], a1r, s6); fma2(acc[1][7], a1r, s7);
            fma2(acc[2][0], a2, s0); fma2(acc[2][1], a2, s1); fma2(acc[2][2], a2, s2); fma2(acc[2][3], a2, s3);
            fma2(acc[2][4], a2, s4); fma2(acc[2][5], a2, s5); fma2(acc[2][6], a2, s6); fma2(acc[2][7], a2, s7);
            fma2(acc[3][0], a3, s0); fma2(acc[3][1], a3, s1); fma2(acc[3][2], a3, s2); fma2(acc[3][3], a3, s3);
            fma2(acc[3][4], a3, s4); fma2(acc[3][5], a3, s5); fma2(acc[3][6], a3, s6); fma2(acc[3][7], a3, s7);
        }
        __syncthreads();
    }

    int hA = 2 * by, hB = 2 * by + 1;
    float4 biasA = *(const float4*)&b[hA * NH + tx * 4];
    float4 biasB = *(const float4*)&b[hB * NH + tx * 4];

    const float* aA = a1 + hA * 2 * NH;
    const float* aB = a1 + hB * 2 * NH;
    ull apA[4], apB[4];
#pragma unroll
    for (int q = 0; q < 4; q++) {
        apA[q] = pack2(aA[tx * 4 + q], aA[NH + tx * 4 + q]);
        apB[q] = pack2(aB[tx * 4 + q], aB[NH + tx * 4 + q]);
    }

#pragma unroll
    for (int p = 0; p < 4; p++) {
        int mlo = m0 + ty * 8 + 2 * p;
        float2 c0 = unpack2(acc[p][0]), c1 = unpack2(acc[p][1]);
        float2 c2 = unpack2(acc[p][2]), c3 = unpack2(acc[p][3]);
        float2 c4 = unpack2(acc[p][4]), c5 = unpack2(acc[p][5]);
        float2 c6 = unpack2(acc[p][6]), c7 = unpack2(acc[p][7]);
        float4 vA0 = make_float4(c0.x + biasA.x, c1.x + biasA.y, c2.x + biasA.z, c3.x + biasA.w);
        float4 vA1 = make_float4(c0.y + biasA.x, c1.y + biasA.y, c2.y + biasA.z, c3.y + biasA.w);
        float4 vB0 = make_float4(c4.x + biasB.x, c5.x + biasB.y, c6.x + biasB.z, c7.x + biasB.w);
        float4 vB1 = make_float4(c4.y + biasB.x, c5.y + biasB.y, c6.y + biasB.z, c7.y + biasB.w);

        // fp16 stores of Wh1 (4 halves = 8B per row-slice)
        *(ull*)&g_Wh1h[((size_t)hA * NN + mlo)     * NH + tx * 4] =
            ((ull)f2h2(vA0.z, vA0.w) << 32) | f2h2(vA0.x, vA0.y);
        *(ull*)&g_Wh1h[((size_t)hA * NN + mlo + 1) * NH + tx * 4] =
            ((ull)f2h2(vA1.z, vA1.w) << 32) | f2h2(vA1.x, vA1.y);
        *(ull*)&g_Wh1h[((size_t)hB * NN + mlo)     * NH + tx * 4] =
            ((ull)f2h2(vB0.z, vB0.w) << 32) | f2h2(vB0.x, vB0.y);
        *(ull*)&g_Wh1h[((size_t)hB * NN + mlo + 1) * NH + tx * 4] =
            ((ull)f2h2(vB1.z, vB1.w) << 32) | f2h2(vB1.x, vB1.y);

        // fused src/dst partial dots (fp32) + 16-lane butterfly
        ull sdA0 = 0ull, sdA1 = 0ull, sdB0 = 0ull, sdB1 = 0ull;
        fma2(sdA0, splat2(vA0.x), apA[0]); fma2(sdA0, splat2(vA0.y), apA[1]);
        fma2(sdA0, splat2(vA0.z), apA[2]); fma2(sdA0, splat2(vA0.w), apA[3]);
        fma2(sdA1, splat2(vA1.x), apA[0]); fma2(sdA1, splat2(vA1.y), apA[1]);
        fma2(sdA1, splat2(vA1.z), apA[2]); fma2(sdA1, splat2(vA1.w), apA[3]);
        fma2(sdB0, splat2(vB0.x), apB[0]); fma2(sdB0, splat2(vB0.y), apB[1]);
        fma2(sdB0, splat2(vB0.z), apB[2]); fma2(sdB0, splat2(vB0.w), apB[3]);
        fma2(sdB1, splat2(vB1.x), apB[0]); fma2(sdB1, splat2(vB1.y), apB[1]);
        fma2(sdB1, splat2(vB1.z), apB[2]); fma2(sdB1, splat2(vB1.w), apB[3]);
        sdA0 = halfSum2(sdA0); sdA1 = halfSum2(sdA1);
        sdB0 = halfSum2(sdB0); sdB1 = halfSum2(sdB1);
        if (tx == 0) {
            float2 r;
            r = unpack2(sdA0); g_srcT1[mlo * 4 + hA]       = r.x; g_dstT1[mlo * 4 + hA]       = r.y;
            r = unpack2(sdA1); g_srcT1[(mlo + 1) * 4 + hA] = r.x; g_dstT1[(mlo + 1) * 4 + hA] = r.y;
            r = unpack2(sdB0); g_srcT1[mlo * 4 + hB]       = r.x; g_dstT1[mlo * 4 + hB]       = r.y;
            r = unpack2(sdB1); g_srcT1[(mlo + 1) * 4 + hB] = r.x; g_dstT1[(mlo + 1) * 4 + hB] = r.y;
        }
    }
}

// ---------------- layer-1 sparse attention + elu + concat ----------------
// block 128 = one row. Block-wide gather (with dstT1 float4 prefetch to smem),
// CSR list written to global for att2; per-head warps do softmax + fp16-Wh
// aggregation with fp32 accumulation.
__global__ __launch_bounds__(128) void k_att1(const float* __restrict__ ab1) {
    __shared__ unsigned short s_nbr[CAP];
    __shared__ float4         s_dst[CAP];
    __shared__ float          s_p[4][CAP];
    __shared__ int            s_wtot[4];
    int i = blockIdx.x;
    int t = threadIdx.x;
    int h = t >> 5, lane = t & 31;
    int half = lane >> 4, sl = lane & 15;

    const unsigned* row = g_adj + (size_t)i * ADJW;

    unsigned w = row[t];
    int c = __popc(w);
    int ofs = c;
#pragma unroll
    for (int o = 1; o < 32; o <<= 1) {
        int v = __shfl_up_sync(0xffffffffu, ofs, o);
        if (lane >= o) ofs += v;
    }
    if (lane == 31) s_wtot[h] = ofs;
    __syncthreads();
    int wbase = 0;
#pragma unroll
    for (int q = 0; q < 4; q++) wbase += (q < h) ? s_wtot[q] : 0;
    int cnt = s_wtot[0] + s_wtot[1] + s_wtot[2] + s_wtot[3];
    int base = wbase + ofs - c;
    while (w) {
        int bb = __ffs(w) - 1; w &= w - 1;
        int j = t * 32 + bb;
        if (base < CAP) {
            s_nbr[base] = (unsigned short)j;
            s_dst[base] = *(const float4*)&g_dstT1[j * 4];
        }
        base++;
    }
    __syncthreads();

    if (t == 0) g_cnt[i] = cnt;
    int cc = cnt < CAP ? cnt : CAP;
    for (int k = t; k < cc; k += 128) g_nbr[i * CAP + k] = s_nbr[k];

    float srci = g_srcT1[i * 4 + h] + ab1[h];
    const unsigned short* Whh = g_Wh1h + (size_t)h * NN * NH;
    ull accA = 0ull, accB = 0ull; float sden;

    if (cnt > 0 && cnt <= CAP) {
        float m = -1e30f;
        for (int k = lane; k < cnt; k += 32) {
            float e = srci + ((const float*)&s_dst[k])[h];
            e = e > 0.f ? e : ALPHA * e;
            s_p[h][k] = e;
            m = fmaxf(m, e);
        }
        m = warpMax(m);
        float s = 0.f;
        for (int k = lane; k < cnt; k += 32) {
            float p = __expf(s_p[h][k] - m); s_p[h][k] = p; s += p;
        }
        sden = warpSum(s);
        __syncwarp();
#pragma unroll 4
        for (int k = half; k < cnt; k += 2) {
            float p = s_p[h][k];
            int j = s_nbr[k];
            ull wv = *(const ull*)(Whh + (size_t)j * NH + sl * 4);
            float2 f0 = h2f((unsigned)wv);
            float2 f1 = h2f((unsigned)(wv >> 32));
            ull ps = splat2(p);
            fma2(accA, ps, pack2(f0.x, f0.y));
            fma2(accB, ps, pack2(f1.x, f1.y));
        }
    } else if (cnt == 0) {
        ull one = splat2(1.f);
#pragma unroll 4
        for (int j = half; j < NN; j += 2) {
            ull wv = *(const ull*)(Whh + (size_t)j * NH + sl * 4);
            float2 f0 = h2f((unsigned)wv);
            float2 f1 = h2f((unsigned)(wv >> 32));
            fma2(accA, one, pack2(f0.x, f0.y));
            fma2(accB, one, pack2(f1.x, f1.y));
        }
        sden = (float)NN;
    } else {
        float m = -1e30f;
        for (int j = 0; j < NN; j++)
            if ((row[j >> 5] >> (j & 31)) & 1u) {
                float e = srci + g_dstT1[j * 4 + h]; e = e > 0.f ? e : ALPHA * e;
                m = fmaxf(m, e);
            }
        sden = 0.f;
        for (int j = 0; j < NN; j++)
            if ((row[j >> 5] >> (j & 31)) & 1u) {
                float e = srci + g_dstT1[j * 4 + h]; e = e > 0.f ? e : ALPHA * e;
                float p = __expf(e - m); sden += p;
                if (half == 0) {
                    ull wv = *(const ull*)(Whh + (size_t)j * NH + sl * 4);
                    float2 f0 = h2f((unsigned)wv);
                    float2 f1 = h2f((unsigned)(wv >> 32));
                    ull ps = splat2(p);
                    fma2(accA, ps, pack2(f0.x, f0.y));
                    fma2(accB, ps, pack2(f1.x, f1.y));
                }
            }
    }
    accA = add2(accA, __shfl_xor_sync(0xffffffffu, accA, 16));
    accB = add2(accB, __shfl_xor_sync(0xffffffffu, accB, 16));
    if (half == 0) {
        float inv = 1.f / sden;
        float2 a = unpack2(accA), bb = unpack2(accB);
        float4 v = make_float4(a.x * inv, a.y * inv, bb.x * inv, bb.y * inv);
        v.x = v.x > 0.f ? v.x : expm1f(v.x);
        v.y = v.y > 0.f ? v.y : expm1f(v.y);
        v.z = v.z > 0.f ? v.z : expm1f(v.z);
        v.w = v.w > 0.f ? v.w : expm1f(v.w);
        *(float4*)&g_h[(size_t)i * (HEADS * NH) + h * NH + sl * 4] = v;
    }
}

// ---------------- layer-2 GEMM + src/dst fold -----------------------------
__global__ __launch_bounds__(256) void k_gemm2(const float* __restrict__ Wo,
                                               const float* __restrict__ bo,
                                               const float* __restrict__ ao) {
    __shared__ float sW[256 * NC];
    int tid = threadIdx.x;
#pragma unroll
    for (int q = 0; q < 10; q++) {
        int f = tid + q * 256;
        *(float4*)&sW[f * 4] = *(const float4*)&Wo[f * 4];
    }
    __syncthreads();

    int m  = blockIdx.x * 64 + (tid >> 2);
    int g  = tid & 3;
    int cp0 = g * 5;
    const float* hr = g_h + (size_t)m * (HEADS * NH);

    ull acc[5];
#pragma unroll
    for (int u = 0; u < 5; u++)
        acc[u] = pack2(bo[2 * (cp0 + u)], bo[2 * (cp0 + u) + 1]);

    for (int k0 = 0; k0 < HEADS * NH; k0 += 4) {
        float4 hv = *(const float4*)(hr + k0);
#pragma unroll
        for (int q = 0; q < 4; q++) {
            float hvq = q == 0 ? hv.x : q == 1 ? hv.y : q == 2 ? hv.z : hv.w;
            ull hs = splat2(hvq);
            const float* wrow = sW + (k0 + q) * NC + 2 * cp0;
#pragma unroll
            for (int u = 0; u < 5; u++)
                fma2(acc[u], hs, *(const ull*)(wrow + 2 * u));
        }
    }

    float sp = 0.f, tp = 0.f;
#pragma unroll
    for (int u = 0; u < 5; u++) {
        float2 p = unpack2(acc[u]);
        int c = 2 * (cp0 + u);
        sp += p.x * ao[c]      + p.y * ao[c + 1];
        tp += p.x * ao[NC + c] + p.y * ao[NC + c + 1];
        *(float2*)&g_Wh2[(size_t)m * NC + c] = p;
    }
    sp += __shfl_xor_sync(0xffffffffu, sp, 1);
    sp += __shfl_xor_sync(0xffffffffu, sp, 2);
    tp += __shfl_xor_sync(0xffffffffu, tp, 1);
    tp += __shfl_xor_sync(0xffffffffu, tp, 2);
    if (g == 0) { g_src2[m] = sp; g_dst2[m] = tp; }
}

// ---------------- output attention + elu + log_softmax ----------------
__global__ __launch_bounds__(128) void k_att2(const float* __restrict__ abo,
                                              float* __restrict__ out) {
    __shared__ float          s_pe[4][CAP];
    __shared__ unsigned short s_nb[4][CAP];
    int wi = threadIdx.x >> 5;
    int i  = blockIdx.x * 4 + wi;
    int lane = threadIdx.x & 31;

    int cnt = g_cnt[i];
    float srci = g_src2[i] + abo[0];

    bool act = lane < NC / 2;
    ull acc = 0ull; float sden;

    if (cnt > 0 && cnt <= CAP) {
        const unsigned short* nb = g_nbr + i * CAP;
        float m = -1e30f;
        for (int k = lane; k < cnt; k += 32) {
            int j = nb[k];
            s_nb[wi][k] = (unsigned short)j;
            float e = srci + g_dst2[j];
            e = e > 0.f ? e : ALPHA * e;
            s_pe[wi][k] = e;
            m = fmaxf(m, e);
        }
        m = warpMax(m);
        float s = 0.f;
        for (int k = lane; k < cnt; k += 32) {
            float p = __expf(s_pe[wi][k] - m); s_pe[wi][k] = p; s += p;
        }
        sden = warpSum(s);
        __syncwarp();
#pragma unroll 4
        for (int k = 0; k < cnt; k++) {
            float p = s_pe[wi][k];
            int j = s_nb[wi][k];
            if (act) {
                ull wv = *(const ull*)(g_Wh2 + (size_t)j * NC + 2 * lane);
                fma2(acc, splat2(p), wv);
            }
        }
    } else if (cnt == 0) {
        ull one = splat2(1.f);
        for (int j = 0; j < NN; j++)
            if (act) {
                ull wv = *(const ull*)(g_Wh2 + (size_t)j * NC + 2 * lane);
                fma2(acc, one, wv);
            }
        sden = (float)NN;
    } else {
        const unsigned* row = g_adj + (size_t)i * ADJW;
        float m = -1e30f;
        for (int j = 0; j < NN; j++)
            if ((row[j >> 5] >> (j & 31)) & 1u) {
                float e = srci + g_dst2[j]; e = e > 0.f ? e : ALPHA * e;
                m = fmaxf(m, e);
            }
        sden = 0.f;
        for (int j = 0; j < NN; j++)
            if ((row[j >> 5] >> (j & 31)) & 1u) {
                float e = srci + g_dst2[j]; e = e > 0.f ? e : ALPHA * e;
                float p = __expf(e - m); sden += p;
                if (act) {
                    ull wv = *(const ull*)(g_Wh2 + (size_t)j * NC + 2 * lane);
                    fma2(acc, splat2(p), wv);
                }
            }
    }
    float inv = 1.f / sden;
    float2 v = unpack2(acc);
    v.x *= inv; v.y *= inv;
    if (act) {
        v.x = v.x > 0.f ? v.x : expm1f(v.x);
        v.y = v.y > 0.f ? v.y : expm1f(v.y);
    }
    float mx = act ? fmaxf(v.x, v.y) : -1e30f;
    mx = warpMax(mx);
    float se = act ? (__expf(v.x - mx) + __expf(v.y - mx)) : 0.f;
    se = warpSum(se);
    float ls = mx + __logf(se);

    if (act)
        *(float2*)&out[(size_t)i * NC + 2 * lane] = make_float2(v.x - ls, v.y - ls);
}

// ---------------- launcher ----------------
extern "C" void kernel_launch(void* const* d_in, const int* in_sizes, int n_in,
                              void* d_out, int out_size) {
    const float* x   = (const float*)d_in[0];
    const void*  ei  = d_in[1];
    const float* W1  = (const float*)d_in[2];
    const float* b1  = (const float*)d_in[3];
    const float* a1  = (const float*)d_in[4];
    const float* ab1 = (const float*)d_in[5];
    const float* Wo  = (const float*)d_in[6];
    const float* bo  = (const float*)d_in[7];
    const float* ao  = (const float*)d_in[8];
    const float* abo = (const float*)d_in[9];
    float* out = (float*)d_out;

    k_zero<<<NN * ADJW / 4 / 256, 256>>>();
    k_scatter<<<NE / 256, 256>>>(ei);
    k_gemm1<<<dim3(64, 2), 128>>>(x, W1, b1, a1);
    k_att1<<<NN, 128>>>(ab1);
    k_gemm2<<<64, 256>>>(Wo, bo, ao);
    k_att2<<<NN / 4, 128>>>(abo, out);
}

// round 16
// speedup vs baseline: 1.1291x; 1.0504x over previous
#include <cuda_runtime.h>
#include <math.h>

#define NN    4096
#define NF    512
#define NH    64
#define NC    40
#define HEADS 4
#define NE    131072
#define ADJW  128          // 4096 bits / 32 per row
#define CAP   192          // neighbor capacity (mean deg 32)
#define ALPHA 0.2f

typedef unsigned long long ull;

// ---------------- scratch (device globals; no allocation allowed) ----------
// g_adj starts BSS-zeroed; every execution re-zeroes it at the end of k_att2,
// so each graph replay sees a clean bitmask.
__device__ __align__(16) unsigned       g_adj[NN * ADJW];
__device__ __align__(16) unsigned short g_Wh1h[HEADS * NN * NH];  // fp16 Wh1
__device__ __align__(16) float          g_srcT1[NN * HEADS];  // [i][h]
__device__ __align__(16) float          g_dstT1[NN * HEADS];  // [i][h]
__device__ __align__(16) float          g_h[NN * HEADS * NH];
__device__ __align__(16) float          g_Wh2[NN * NC];
__device__ __align__(16) float          g_src2[NN];
__device__ __align__(16) float          g_dst2[NN];
__device__ __align__(16) unsigned short g_nbr[NN * CAP];      // CSR handoff
__device__                int           g_cnt[NN];

// ---------------- packed f32x2 helpers ----------------
__device__ __forceinline__ void fma2(ull& acc, ull a, ull b) {
    asm("fma.rn.f32x2 %0, %1, %2, %0;" : "+l"(acc) : "l"(a), "l"(b));
}
__device__ __forceinline__ ull add2(ull a, ull b) {
    ull r; asm("add.rn.f32x2 %0, %1, %2;" : "=l"(r) : "l"(a), "l"(b)); return r;
}
__device__ __forceinline__ ull splat2(float v) {
    ull r; asm("mov.b64 %0, {%1, %1};" : "=l"(r) : "f"(v)); return r;
}
__device__ __forceinline__ ull pack2(float lo, float hi) {
    ull r; asm("mov.b64 %0, {%1, %2};" : "=l"(r) : "f"(lo), "f"(hi)); return r;
}
__device__ __forceinline__ float2 unpack2(ull v) {
    float2 r; asm("mov.b64 {%0, %1}, %2;" : "=f"(r.x), "=f"(r.y) : "l"(v)); return r;
}

// ---------------- fp16 pack/unpack (header-free) ----------------
__device__ __forceinline__ unsigned f2h2(float lo, float hi) {
    unsigned r;
    asm("cvt.rn.f16x2.f32 %0, %1, %2;" : "=r"(r) : "f"(hi), "f"(lo));
    return r;
}
__device__ __forceinline__ float2 h2f(unsigned h) {
    float2 r;
    asm("{.reg .f16 l, u; mov.b32 {l, u}, %2; cvt.f32.f16 %0, l; cvt.f32.f16 %1, u;}" : "=f"(r.x), "=f"(r.y) : "r"(h));
    return r;
}

// ---------------- warp reductions ----------------
__device__ __forceinline__ float warpMax(float v) {
#pragma unroll
    for (int o = 16; o; o >>= 1) v = fmaxf(v, __shfl_xor_sync(0xffffffffu, v, o));
    return v;
}
__device__ __forceinline__ float warpSum(float v) {
#pragma unroll
    for (int o = 16; o; o >>= 1) v += __shfl_xor_sync(0xffffffffu, v, o);
    return v;
}
__device__ __forceinline__ ull halfSum2(ull v) {
#pragma unroll
    for (int o = 1; o <= 8; o <<= 1)
        v = add2(v, __shfl_xor_sync(0xffffffffu, v, o));
    return v;
}

// ---------------- layer-1 GEMM + fused src/dst epilogue + scatter ----------
// grid (64, 3), 128 threads. by<2: 64x128 GEMM tile (2 heads), thread = 8m x
// 8n f32x2, fp16 Wh1 stores, fp32 src/dst fold. by==2: adjacency scatter
// (overlapped under the GEMM blocks; same-kernel boundary orders it before
// k_att1).
__global__ __launch_bounds__(128) void k_gemm1(const float* __restrict__ x,
                                               const float* __restrict__ W,
                                               const float* __restrict__ b,
                                               const float* __restrict__ a1,
                                               const void* __restrict__ ei) {
    __shared__ float As[2][16][68];
    __shared__ float Bs[2][16][128];
    int t  = threadIdx.x;
    int by = blockIdx.y;

    if (by == 2) {
        // ---- adjacency scatter: 64 blocks x 128 threads x 16 edges ----
        const long long* p64 = (const long long*)ei;
        bool is32 = false;
#pragma unroll
        for (int q = 0; q < 16; q++) {
            long long v = p64[q];
            if (v < 0 || v >= NN) is32 = true;
        }
        int base = blockIdx.x * 2048 + t;
#pragma unroll
        for (int q = 0; q < 16; q++) {
            int k = base + q * 128;
            int s, d;
            if (is32) {
                const int* p = (const int*)ei;
                s = p[k]; d = p[k + NE];
            } else {
                s = (int)p64[k]; d = (int)p64[k + NE];
            }
            atomicOr(&g_adj[s * ADJW + (d >> 5)], 1u << (d & 31));
        }
        return;
    }

    int tx = t & 15, ty = t >> 4;
    int m0 = blockIdx.x * 64;
    const float* W0  = W + (size_t)(2 * by) * NF * NH;
    const float* W1p = W0 + (size_t)NF * NH;

    const float* xp  = x + (size_t)(m0 + (t >> 1)) * NF + (t & 1) * 8;
    const float* bp0 = W0  + (size_t)ty * NH + tx * 4;
    const float* bp1 = W1p + (size_t)ty * NH + tx * 4;

    float4 ra0 = *(const float4*)(xp);
    float4 ra1 = *(const float4*)(xp + 4);
    float4 rb0 = *(const float4*)(bp0);
    float4 rb1 = *(const float4*)(bp0 + 8 * NH);
    float4 rb2 = *(const float4*)(bp1);
    float4 rb3 = *(const float4*)(bp1 + 8 * NH);

    ull acc[4][8];
#pragma unroll
    for (int p = 0; p < 4; p++)
#pragma unroll
        for (int j = 0; j < 8; j++) acc[p][j] = 0ull;

    int kh = (t & 1) * 8, mA = t >> 1;

    for (int ch = 0; ch < 32; ch++) {
        int bi = ch & 1;
        As[bi][kh + 0][mA] = ra0.x; As[bi][kh + 1][mA] = ra0.y;
        As[bi][kh + 2][mA] = ra0.z; As[bi][kh + 3][mA] = ra0.w;
        As[bi][kh + 4][mA] = ra1.x; As[bi][kh + 5][mA] = ra1.y;
        As[bi][kh + 6][mA] = ra1.z; As[bi][kh + 7][mA] = ra1.w;
        *(float4*)&Bs[bi][ty    ][tx * 4]      = rb0;
        *(float4*)&Bs[bi][ty + 8][tx * 4]      = rb1;
        *(float4*)&Bs[bi][ty    ][64 + tx * 4] = rb2;
        *(float4*)&Bs[bi][ty + 8][64 + tx * 4] = rb3;
        __syncthreads();
        if (ch < 31) {
            int ko = (ch + 1) * 16;
            ra0 = *(const float4*)(xp + ko);
            ra1 = *(const float4*)(xp + ko + 4);
            rb0 = *(const float4*)(bp0 + (size_t)ko * NH);
            rb1 = *(const float4*)(bp0 + (size_t)(ko + 8) * NH);
            rb2 = *(const float4*)(bp1 + (size_t)ko * NH);
            rb3 = *(const float4*)(bp1 + (size_t)(ko + 8) * NH);
        }
#pragma unroll
        for (int kk = 0; kk < 16; kk++) {
            ull a0 = *(const ull*)&As[bi][kk][ty * 8 + 0];
            ull a1r = *(const ull*)&As[bi][kk][ty * 8 + 2];
            ull a2 = *(const ull*)&As[bi][kk][ty * 8 + 4];
            ull a3 = *(const ull*)&As[bi][kk][ty * 8 + 6];
            float4 v0 = *(const float4*)&Bs[bi][kk][tx * 4];
            float4 v1 = *(const float4*)&Bs[bi][kk][64 + tx * 4];
            ull s0 = splat2(v0.x), s1 = splat2(v0.y), s2 = splat2(v0.z), s3 = splat2(v0.w);
            ull s4 = splat2(v1.x), s5 = splat2(v1.y), s6 = splat2(v1.z), s7 = splat2(v1.w);
            fma2(acc[0][0], a0, s0); fma2(acc[0][1], a0, s1); fma2(acc[0][2], a0, s2); fma2(acc[0][3], a0, s3);
            fma2(acc[0][4], a0, s4); fma2(acc[0][5], a0, s5); fma2(acc[0][6], a0, s6); fma2(acc[0][7], a0, s7);
            fma2(acc[1][0], a1r, s0); fma2(acc[1][1], a1r, s1); fma2(acc[1][2], a1r, s2); fma2(acc[1][3], a1r, s3);
            fma2(acc[1][4], a1r, s4); fma2(acc[1][5], a1r, s5); fma2(acc[1][6], a1r, s6); fma2(acc[1][7], a1r, s7);
            fma2(acc[2][0], a2, s0); fma2(acc[2][1], a2, s1); fma2(acc[2][2], a2, s2); fma2(acc[2][3], a2, s3);
            fma2(acc[2][4], a2, s4); fma2(acc[2][5], a2, s5); fma2(acc[2][6], a2, s6); fma2(acc[2][7], a2, s7);
            fma2(acc[3][0], a3, s0); fma2(acc[3][1], a3, s1); fma2(acc[3][2], a3, s2); fma2(acc[3][3], a3, s3);
            fma2(acc[3][4], a3, s4); fma2(acc[3][5], a3, s5); fma2(acc[3][6], a3, s6); fma2(acc[3][7], a3, s7);
        }
        __syncthreads();
    }

    int hA = 2 * by, hB = 2 * by + 1;
    float4 biasA = *(const float4*)&b[hA * NH + tx * 4];
    float4 biasB = *(const float4*)&b[hB * NH + tx * 4];

    const float* aA = a1 + hA * 2 * NH;
    const float* aB = a1 + hB * 2 * NH;
    ull apA[4], apB[4];
#pragma unroll
    for (int q = 0; q < 4; q++) {
        apA[q] = pack2(aA[tx * 4 + q], aA[NH + tx * 4 + q]);
        apB[q] = pack2(aB[tx * 4 + q], aB[NH + tx * 4 + q]);
    }

#pragma unroll
    for (int p = 0; p < 4; p++) {
        int mlo = m0 + ty * 8 + 2 * p;
        float2 c0 = unpack2(acc[p][0]), c1 = unpack2(acc[p][1]);
        float2 c2 = unpack2(acc[p][2]), c3 = unpack2(acc[p][3]);
        float2 c4 = unpack2(acc[p][4]), c5 = unpack2(acc[p][5]);
        float2 c6 = unpack2(acc[p][6]), c7 = unpack2(acc[p][7]);
        float4 vA0 = make_float4(c0.x + biasA.x, c1.x + biasA.y, c2.x + biasA.z, c3.x + biasA.w);
        float4 vA1 = make_float4(c0.y + biasA.x, c1.y + biasA.y, c2.y + biasA.z, c3.y + biasA.w);
        float4 vB0 = make_float4(c4.x + biasB.x, c5.x + biasB.y, c6.x + biasB.z, c7.x + biasB.w);
        float4 vB1 = make_float4(c4.y + biasB.x, c5.y + biasB.y, c6.y + biasB.z, c7.y + biasB.w);

        *(ull*)&g_Wh1h[((size_t)hA * NN + mlo)     * NH + tx * 4] =
            ((ull)f2h2(vA0.z, vA0.w) << 32) | f2h2(vA0.x, vA0.y);
        *(ull*)&g_Wh1h[((size_t)hA * NN + mlo + 1) * NH + tx * 4] =
            ((ull)f2h2(vA1.z, vA1.w) << 32) | f2h2(vA1.x, vA1.y);
        *(ull*)&g_Wh1h[((size_t)hB * NN + mlo)     * NH + tx * 4] =
            ((ull)f2h2(vB0.z, vB0.w) << 32) | f2h2(vB0.x, vB0.y);
        *(ull*)&g_Wh1h[((size_t)hB * NN + mlo + 1) * NH + tx * 4] =
            ((ull)f2h2(vB1.z, vB1.w) << 32) | f2h2(vB1.x, vB1.y);

        ull sdA0 = 0ull, sdA1 = 0ull, sdB0 = 0ull, sdB1 = 0ull;
        fma2(sdA0, splat2(vA0.x), apA[0]); fma2(sdA0, splat2(vA0.y), apA[1]);
        fma2(sdA0, splat2(vA0.z), apA[2]); fma2(sdA0, splat2(vA0.w), apA[3]);
        fma2(sdA1, splat2(vA1.x), apA[0]); fma2(sdA1, splat2(vA1.y), apA[1]);
        fma2(sdA1, splat2(vA1.z), apA[2]); fma2(sdA1, splat2(vA1.w), apA[3]);
        fma2(sdB0, splat2(vB0.x), apB[0]); fma2(sdB0, splat2(vB0.y), apB[1]);
        fma2(sdB0, splat2(vB0.z), apB[2]); fma2(sdB0, splat2(vB0.w), apB[3]);
        fma2(sdB1, splat2(vB1.x), apB[0]); fma2(sdB1, splat2(vB1.y), apB[1]);
        fma2(sdB1, splat2(vB1.z), apB[2]); fma2(sdB1, splat2(vB1.w), apB[3]);
        sdA0 = halfSum2(sdA0); sdA1 = halfSum2(sdA1);
        sdB0 = halfSum2(sdB0); sdB1 = halfSum2(sdB1);
        if (tx == 0) {
            float2 r;
            r = unpack2(sdA0); g_srcT1[mlo * 4 + hA]       = r.x; g_dstT1[mlo * 4 + hA]       = r.y;
            r = unpack2(sdA1); g_srcT1[(mlo + 1) * 4 + hA] = r.x; g_dstT1[(mlo + 1) * 4 + hA] = r.y;
            r = unpack2(sdB0); g_srcT1[mlo * 4 + hB]       = r.x; g_dstT1[mlo * 4 + hB]       = r.y;
            r = unpack2(sdB1); g_srcT1[(mlo + 1) * 4 + hB] = r.x; g_dstT1[(mlo + 1) * 4 + hB] = r.y;
        }
    }
}

// ---------------- layer-1 sparse attention + elu + concat ----------------
__global__ __launch_bounds__(128) void k_att1(const float* __restrict__ ab1) {
    __shared__ unsigned short s_nbr[CAP];
    __shared__ float4         s_dst[CAP];
    __shared__ float          s_p[4][CAP];
    __shared__ int            s_wtot[4];
    int i = blockIdx.x;
    int t = threadIdx.x;
    int h = t >> 5, lane = t & 31;
    int half = lane >> 4, sl = lane & 15;

    const unsigned* row = g_adj + (size_t)i * ADJW;

    unsigned w = row[t];
    int c = __popc(w);
    int ofs = c;
#pragma unroll
    for (int o = 1; o < 32; o <<= 1) {
        int v = __shfl_up_sync(0xffffffffu, ofs, o);
        if (lane >= o) ofs += v;
    }
    if (lane == 31) s_wtot[h] = ofs;
    __syncthreads();
    int wbase = 0;
#pragma unroll
    for (int q = 0; q < 4; q++) wbase += (q < h) ? s_wtot[q] : 0;
    int cnt = s_wtot[0] + s_wtot[1] + s_wtot[2] + s_wtot[3];
    int base = wbase + ofs - c;
    while (w) {
        int bb = __ffs(w) - 1; w &= w - 1;
        int j = t * 32 + bb;
        if (base < CAP) {
            s_nbr[base] = (unsigned short)j;
            s_dst[base] = *(const float4*)&g_dstT1[j * 4];
        }
        base++;
    }
    __syncthreads();

    if (t == 0) g_cnt[i] = cnt;
    int cc = cnt < CAP ? cnt : CAP;
    for (int k = t; k < cc; k += 128) g_nbr[i * CAP + k] = s_nbr[k];

    float srci = g_srcT1[i * 4 + h] + ab1[h];
    const unsigned short* Whh = g_Wh1h + (size_t)h * NN * NH;
    ull accA = 0ull, accB = 0ull; float sden;

    if (cnt > 0 && cnt <= CAP) {
        float m = -1e30f;
        for (int k = lane; k < cnt; k += 32) {
            float e = srci + ((const float*)&s_dst[k])[h];
            e = e > 0.f ? e : ALPHA * e;
            s_p[h][k] = e;
            m = fmaxf(m, e);
        }
        m = warpMax(m);
        float s = 0.f;
        for (int k = lane; k < cnt; k += 32) {
            float p = __expf(s_p[h][k] - m); s_p[h][k] = p; s += p;
        }
        sden = warpSum(s);
        __syncwarp();
#pragma unroll 4
        for (int k = half; k < cnt; k += 2) {
            float p = s_p[h][k];
            int j = s_nbr[k];
            ull wv = *(const ull*)(Whh + (size_t)j * NH + sl * 4);
            float2 f0 = h2f((unsigned)wv);
            float2 f1 = h2f((unsigned)(wv >> 32));
            ull ps = splat2(p);
            fma2(accA, ps, pack2(f0.x, f0.y));
            fma2(accB, ps, pack2(f1.x, f1.y));
        }
    } else if (cnt == 0) {
        ull one = splat2(1.f);
#pragma unroll 4
        for (int j = half; j < NN; j += 2) {
            ull wv = *(const ull*)(Whh + (size_t)j * NH + sl * 4);
            float2 f0 = h2f((unsigned)wv);
            float2 f1 = h2f((unsigned)(wv >> 32));
            fma2(accA, one, pack2(f0.x, f0.y));
            fma2(accB, one, pack2(f1.x, f1.y));
        }
        sden = (float)NN;
    } else {
        float m = -1e30f;
        for (int j = 0; j < NN; j++)
            if ((row[j >> 5] >> (j & 31)) & 1u) {
                float e = srci + g_dstT1[j * 4 + h]; e = e > 0.f ? e : ALPHA * e;
                m = fmaxf(m, e);
            }
        sden = 0.f;
        for (int j = 0; j < NN; j++)
            if ((row[j >> 5] >> (j & 31)) & 1u) {
                float e = srci + g_dstT1[j * 4 + h]; e = e > 0.f ? e : ALPHA * e;
                float p = __expf(e - m); sden += p;
                if (half == 0) {
                    ull wv = *(const ull*)(Whh + (size_t)j * NH + sl * 4);
                    float2 f0 = h2f((unsigned)wv);
                    float2 f1 = h2f((unsigned)(wv >> 32));
                    ull ps = splat2(p);
                    fma2(accA, ps, pack2(f0.x, f0.y));
                    fma2(accB, ps, pack2(f1.x, f1.y));
                }
            }
    }
    accA = add2(accA, __shfl_xor_sync(0xffffffffu, accA, 16));
    accB = add2(accB, __shfl_xor_sync(0xffffffffu, accB, 16));
    if (half == 0) {
        float inv = 1.f / sden;
        float2 a = unpack2(accA), bb = unpack2(accB);
        float4 v = make_float4(a.x * inv, a.y * inv, bb.x * inv, bb.y * inv);
        v.x = v.x > 0.f ? v.x : expm1f(v.x);
        v.y = v.y > 0.f ? v.y : expm1f(v.y);
        v.z = v.z > 0.f ? v.z : expm1f(v.z);
        v.w = v.w > 0.f ? v.w : expm1f(v.w);
        *(float4*)&g_h[(size_t)i * (HEADS * NH) + h * NH + sl * 4] = v;
    }
}

// ---------------- layer-2 GEMM + src/dst fold -----------------------------
__global__ __launch_bounds__(256) void k_gemm2(const float* __restrict__ Wo,
                                               const float* __restrict__ bo,
                                               const float* __restrict__ ao) {
    __shared__ float sW[256 * NC];
    int tid = threadIdx.x;
#pragma unroll
    for (int q = 0; q < 10; q++) {
        int f = tid + q * 256;
        *(float4*)&sW[f * 4] = *(const float4*)&Wo[f * 4];
    }
    __syncthreads();

    int m  = blockIdx.x * 64 + (tid >> 2);
    int g  = tid & 3;
    int cp0 = g * 5;
    const float* hr = g_h + (size_t)m * (HEADS * NH);

    ull acc[5];
#pragma unroll
    for (int u = 0; u < 5; u++)
        acc[u] = pack2(bo[2 * (cp0 + u)], bo[2 * (cp0 + u) + 1]);

    for (int k0 = 0; k0 < HEADS * NH; k0 += 4) {
        float4 hv = *(const float4*)(hr + k0);
#pragma unroll
        for (int q = 0; q < 4; q++) {
            float hvq = q == 0 ? hv.x : q == 1 ? hv.y : q == 2 ? hv.z : hv.w;
            ull hs = splat2(hvq);
            const float* wrow = sW + (k0 + q) * NC + 2 * cp0;
#pragma unroll
            for (int u = 0; u < 5; u++)
                fma2(acc[u], hs, *(const ull*)(wrow + 2 * u));
        }
    }

    float sp = 0.f, tp = 0.f;
#pragma unroll
    for (int u = 0; u < 5; u++) {
        float2 p = unpack2(acc[u]);
        int c = 2 * (cp0 + u);
        sp += p.x * ao[c]      + p.y * ao[c + 1];
        tp += p.x * ao[NC + c] + p.y * ao[NC + c + 1];
        *(float2*)&g_Wh2[(size_t)m * NC + c] = p;
    }
    sp += __shfl_xor_sync(0xffffffffu, sp, 1);
    sp += __shfl_xor_sync(0xffffffffu, sp, 2);
    tp += __shfl_xor_sync(0xffffffffu, tp, 1);
    tp += __shfl_xor_sync(0xffffffffu, tp, 2);
    if (g == 0) { g_src2[m] = sp; g_dst2[m] = tp; }
}

// ---------------- output attention + elu + log_softmax + adj clear --------
__global__ __launch_bounds__(128) void k_att2(const float* __restrict__ abo,
                                              float* __restrict__ out) {
    __shared__ float          s_pe[4][CAP];
    __shared__ unsigned short s_nb[4][CAP];
    int wi = threadIdx.x >> 5;
    int i  = blockIdx.x * 4 + wi;
    int lane = threadIdx.x & 31;

    int cnt = g_cnt[i];
    float srci = g_src2[i] + abo[0];

    bool act = lane < NC / 2;
    ull acc = 0ull; float sden;

    if (cnt > 0 && cnt <= CAP) {
        const unsigned short* nb = g_nbr + i * CAP;
        float m = -1e30f;
        for (int k = lane; k < cnt; k += 32) {
            int j = nb[k];
            s_nb[wi][k] = (unsigned short)j;
            float e = srci + g_dst2[j];
            e = e > 0.f ? e : ALPHA * e;
            s_pe[wi][k] = e;
            m = fmaxf(m, e);
        }
        m = warpMax(m);
        float s = 0.f;
        for (int k = lane; k < cnt; k += 32) {
            float p = __expf(s_pe[wi][k] - m); s_pe[wi][k] = p; s += p;
        }
        sden = warpSum(s);
        __syncwarp();
#pragma unroll 4
        for (int k = 0; k < cnt; k++) {
            float p = s_pe[wi][k];
            int j = s_nb[wi][k];
            if (act) {
                ull wv = *(const ull*)(g_Wh2 + (size_t)j * NC + 2 * lane);
                fma2(acc, splat2(p), wv);
            }
        }
    } else if (cnt == 0) {
        ull one = splat2(1.f);
        for (int j = 0; j < NN; j++)
            if (act) {
                ull wv = *(const ull*)(g_Wh2 + (size_t)j * NC + 2 * lane);
                fma2(acc, one, wv);
            }
        sden = (float)NN;
    } else {
        const unsigned* row = g_adj + (size_t)i * ADJW;
        float m = -1e30f;
        for (int j = 0; j < NN; j++)
            if ((row[j >> 5] >> (j & 31)) & 1u) {
                float e = srci + g_dst2[j]; e = e > 0.f ? e : ALPHA * e;
                m = fmaxf(m, e);
            }
        sden = 0.f;
        for (int j = 0; j < NN; j++)
            if ((row[j >> 5] >> (j & 31)) & 1u) {
                float e = srci + g_dst2[j]; e = e > 0.f ? e : ALPHA * e;
                float p = __expf(e - m); sden += p;
                if (act) {
                    ull wv = *(const ull*)(g_Wh2 + (size_t)j * NC + 2 * lane);
                    fma2(acc, splat2(p), wv);
                }
            }
    }
    float inv = 1.f / sden;
    float2 v = unpack2(acc);
    v.x *= inv; v.y *= inv;
    if (act) {
        v.x = v.x > 0.f ? v.x : expm1f(v.x);
        v.y = v.y > 0.f ? v.y : expm1f(v.y);
    }
    float mx = act ? fmaxf(v.x, v.y) : -1e30f;
    mx = warpMax(mx);
    float se = act ? (__expf(v.x - mx) + __expf(v.y - mx)) : 0.f;
    se = warpSum(se);
    float ls = mx + __logf(se);

    if (act)
        *(float2*)&out[(size_t)i * NC + 2 * lane] = make_float2(v.x - ls, v.y - ls);

    // ---- clear adjacency for the next graph replay (one uint4 per thread) ----
    int cidx = blockIdx.x * 128 + threadIdx.x;
    ((uint4*)g_adj)[cidx] = make_uint4(0u, 0u, 0u, 0u);
}

// ---------------- launcher ----------------
extern "C" void kernel_launch(void* const* d_in, const int* in_sizes, int n_in,
                              void* d_out, int out_size) {
    const float* x   = (const float*)d_in[0];
    const void*  ei  = d_in[1];
    const float* W1  = (const float*)d_in[2];
    const float* b1  = (const float*)d_in[3];
    const float* a1  = (const float*)d_in[4];
    const float* ab1 = (const float*)d_in[5];
    const float* Wo  = (const float*)d_in[6];
    const float* bo  = (const float*)d_in[7];
    const float* ao  = (const float*)d_in[8];
    const float* abo = (const float*)d_in[9];
    float* out = (float*)d_out;

    k_gemm1<<<dim3(64, 3), 128>>>(x, W1, b1, a1, ei);
    k_att1<<<NN, 128>>>(ab1);
    k_gemm2<<<64, 256>>>(Wo, bo, ao);
    k_att2<<<NN / 4, 128>>>(abo, out);
}